// round 1
// baseline (speedup 1.0000x reference)
#include <cuda_runtime.h>
#include <cfloat>

#define N_POINTS 32768
#define DIM      256
#define D4       (DIM / 4)
#define K_CODES  4096
#define BM       128
#define BN       64
#define THREADS  512
#define SX       260   // padded smem row stride in floats (16B aligned, low-conflict)

// Scratch (no allocations allowed)
__device__ float  g_csq[K_CODES];
__device__ int    g_idx[N_POINTS];
__device__ double g_acc;

// ---------------------------------------------------------------------------
__global__ void vq_reset_kernel() { g_acc = 0.0; }

// ---------------------------------------------------------------------------
// ||c||^2 per codebook row. One block of 64 threads per row (64 float4 each).
__global__ void vq_csq_kernel(const float* __restrict__ cb) {
    int row = blockIdx.x;
    float4 v = reinterpret_cast<const float4*>(cb + (size_t)row * DIM)[threadIdx.x];
    float s = v.x * v.x + v.y * v.y + v.z * v.z + v.w * v.w;
    #pragma unroll
    for (int o = 16; o > 0; o >>= 1) s += __shfl_xor_sync(0xffffffffu, s, o);
    __shared__ float ws[2];
    if ((threadIdx.x & 31) == 0) ws[threadIdx.x >> 5] = s;
    __syncthreads();
    if (threadIdx.x == 0) g_csq[row] = ws[0] + ws[1];
}

// ---------------------------------------------------------------------------
// Argmin over codes. Block: 128 points x full K sweep. 512 threads.
// Thread (ty = tid/16 in 0..31, tx = tid%16): points {ty + 32*i}, codes {tx + 16*j}.
// score = ||c||^2 - 2*dot  (x^2 term is constant per point, drops out of argmin).
__global__ __launch_bounds__(THREADS, 1)
void vq_argmin_kernel(const float* __restrict__ x, const float* __restrict__ cb) {
    extern __shared__ float smem[];
    float* sX  = smem;               // [BM][SX]
    float* sC  = smem + BM * SX;     // [BN][SX]
    float* scs = sC + BN * SX;       // [BN]

    const int tid = threadIdx.x;
    const int tx  = tid & 15;
    const int ty  = tid >> 4;
    const int pbase = blockIdx.x * BM;

    // Load X tile (128 x 256 fp32) into padded smem
    for (int t = tid; t < BM * D4; t += THREADS) {
        int row = t >> 6, c4 = t & 63;
        float4 v = reinterpret_cast<const float4*>(x)[(size_t)(pbase + row) * D4 + c4];
        *reinterpret_cast<float4*>(&sX[row * SX + c4 * 4]) = v;
    }

    float best[4];
    int   bidx[4];
    #pragma unroll
    for (int i = 0; i < 4; i++) { best[i] = FLT_MAX; bidx[i] = 0; }

    for (int tile = 0; tile < K_CODES / BN; tile++) {
        const int cb_base = tile * BN;
        __syncthreads();  // protect sC/scs from previous iteration's readers
        for (int t = tid; t < BN * D4; t += THREADS) {
            int row = t >> 6, c4 = t & 63;
            float4 v = reinterpret_cast<const float4*>(cb)[(size_t)(cb_base + row) * D4 + c4];
            *reinterpret_cast<float4*>(&sC[row * SX + c4 * 4]) = v;
        }
        if (tid < BN) scs[tid] = g_csq[cb_base + tid];
        __syncthreads();

        float acc[4][4];
        #pragma unroll
        for (int i = 0; i < 4; i++)
            #pragma unroll
            for (int j = 0; j < 4; j++) acc[i][j] = 0.f;

        for (int kc = 0; kc < D4; kc++) {
            float4 xv[4], cv[4];
            #pragma unroll
            for (int i = 0; i < 4; i++)
                xv[i] = *reinterpret_cast<const float4*>(&sX[(ty + i * 32) * SX + kc * 4]);
            #pragma unroll
            for (int j = 0; j < 4; j++)
                cv[j] = *reinterpret_cast<const float4*>(&sC[(tx + j * 16) * SX + kc * 4]);
            #pragma unroll
            for (int i = 0; i < 4; i++)
                #pragma unroll
                for (int j = 0; j < 4; j++) {
                    acc[i][j] = fmaf(xv[i].x, cv[j].x, acc[i][j]);
                    acc[i][j] = fmaf(xv[i].y, cv[j].y, acc[i][j]);
                    acc[i][j] = fmaf(xv[i].z, cv[j].z, acc[i][j]);
                    acc[i][j] = fmaf(xv[i].w, cv[j].w, acc[i][j]);
                }
        }

        // Update per-point best. Ascending j => ascending global code index, so
        // strict < reproduces argmin's first-minimum tie-break within a thread.
        #pragma unroll
        for (int j = 0; j < 4; j++) {
            float cs = scs[tx + j * 16];
            int   gi = cb_base + tx + j * 16;
            #pragma unroll
            for (int i = 0; i < 4; i++) {
                float sc = fmaf(-2.f, acc[i][j], cs);
                if (sc < best[i]) { best[i] = sc; bidx[i] = gi; }
            }
        }
    }

    // Cross-thread (tx) reduction per point; lowest index wins on exact ties.
    __syncthreads();
    float* rs = sC;                       // [BM][16] scores
    int*   ri = reinterpret_cast<int*>(sC + BM * 16);  // [BM][16] indices
    #pragma unroll
    for (int i = 0; i < 4; i++) {
        int p = ty + i * 32;
        rs[p * 16 + tx] = best[i];
        ri[p * 16 + tx] = bidx[i];
    }
    __syncthreads();
    if (tid < BM) {
        int p = tid;
        float bs = rs[p * 16];
        int   bi = ri[p * 16];
        #pragma unroll
        for (int t2 = 1; t2 < 16; t2++) {
            float s  = rs[p * 16 + t2];
            int   ii = ri[p * 16 + t2];
            if (s < bs || (s == bs && ii < bi)) { bs = s; bi = ii; }
        }
        g_idx[pbase + p] = bi;
    }
}

// ---------------------------------------------------------------------------
// Gather quantized rows, emit straight-through output x + (q - x),
// accumulate sum of (q-x)^2 into g_acc.
__global__ void vq_gather_kernel(const float* __restrict__ x,
                                 const float* __restrict__ cb,
                                 float* __restrict__ out) {
    const int total4 = N_POINTS * D4;
    float part = 0.f;
    for (int i4 = blockIdx.x * blockDim.x + threadIdx.x; i4 < total4;
         i4 += gridDim.x * blockDim.x) {
        int p  = i4 >> 6;
        int c4 = i4 & 63;
        int ci = g_idx[p];
        float4 xv = reinterpret_cast<const float4*>(x)[i4];
        float4 qv = reinterpret_cast<const float4*>(cb)[(size_t)ci * D4 + c4];
        float4 d, o;
        d.x = qv.x - xv.x; d.y = qv.y - xv.y; d.z = qv.z - xv.z; d.w = qv.w - xv.w;
        o.x = xv.x + d.x;  o.y = xv.y + d.y;  o.z = xv.z + d.z;  o.w = xv.w + d.w;
        reinterpret_cast<float4*>(out)[i4] = o;
        part += d.x * d.x + d.y * d.y + d.z * d.z + d.w * d.w;
    }
    // block reduce
    #pragma unroll
    for (int o = 16; o > 0; o >>= 1) part += __shfl_xor_sync(0xffffffffu, part, o);
    __shared__ float ws[8];
    if ((threadIdx.x & 31) == 0) ws[threadIdx.x >> 5] = part;
    __syncthreads();
    if (threadIdx.x == 0) {
        float bs = 0.f;
        for (int w = 0; w < (int)(blockDim.x >> 5); w++) bs += ws[w];
        atomicAdd(&g_acc, (double)bs);
    }
}

// ---------------------------------------------------------------------------
__global__ void vq_finalize_kernel(float* __restrict__ out) {
    // loss = q_latent + 0.25 * e_latent; both equal mean((q-x)^2) in value.
    out[(size_t)N_POINTS * DIM] = (float)(1.25 * g_acc / (double)(N_POINTS * DIM));
}

// ---------------------------------------------------------------------------
extern "C" void kernel_launch(void* const* d_in, const int* in_sizes, int n_in,
                              void* d_out, int out_size) {
    const float* x  = (const float*)d_in[0];
    const float* cb = (const float*)d_in[1];
    float* out = (float*)d_out;

    (void)in_sizes; (void)n_in; (void)out_size;

    static bool attr_set = false;
    size_t smem_bytes = (size_t)(BM * SX + BN * SX + BN) * sizeof(float); // ~195 KB
    if (!attr_set) {
        cudaFuncSetAttribute(vq_argmin_kernel,
                             cudaFuncAttributeMaxDynamicSharedMemorySize,
                             (int)smem_bytes);
        attr_set = true;
    }

    vq_reset_kernel<<<1, 1>>>();
    vq_csq_kernel<<<K_CODES, 64>>>(cb);
    vq_argmin_kernel<<<N_POINTS / BM, THREADS, smem_bytes>>>(x, cb);
    vq_gather_kernel<<<2048, 256>>>(x, cb, out);
    vq_finalize_kernel<<<1, 1>>>(out);
}

// round 2
// speedup vs baseline: 1.5725x; 1.5725x over previous
#include <cuda_runtime.h>
#include <cfloat>

#define N_POINTS 32768
#define DIM      256
#define D4       (DIM / 4)
#define K_CODES  4096

#define BM       128
#define BN       256
#define TM       8        // points per thread (4 packed pairs)
#define TN       16       // codes per thread
#define THREADS  256
#define KCHUNK   32       // dims per streamed C chunk
#define NCHUNK   (DIM / KCHUNK)       // 8
#define NTILE    (K_CODES / BN)       // 16
#define SXP      132      // transposed X row stride (floats): 128 pts + pad
#define SCP      36       // C chunk row stride (floats): 32 dims + pad

typedef unsigned long long ull;

// Scratch (no allocations allowed)
__device__ float  g_csq[K_CODES];
__device__ int    g_idx[N_POINTS];
__device__ double g_acc;

// ---------------------------------------------------------------------------
__device__ __forceinline__ ull ffma2(ull a, ull b, ull c) {
    ull d;
    asm("fma.rn.f32x2 %0, %1, %2, %3;" : "=l"(d) : "l"(a), "l"(b), "l"(c));
    return d;
}
__device__ __forceinline__ ull pack2(float v) {
    ull d;
    asm("mov.b64 %0, {%1, %1};" : "=l"(d) : "f"(v));
    return d;
}
__device__ __forceinline__ float2 unpack2(ull v) {
    float2 r;
    asm("mov.b64 {%0, %1}, %2;" : "=f"(r.x), "=f"(r.y) : "l"(v));
    return r;
}
__device__ __forceinline__ void cp_async16(void* dst_smem, const void* src) {
    unsigned sdst = (unsigned)__cvta_generic_to_shared(dst_smem);
    asm volatile("cp.async.cg.shared.global [%0], [%1], 16;" :: "r"(sdst), "l"(src));
}
__device__ __forceinline__ void cp_commit() {
    asm volatile("cp.async.commit_group;" ::: "memory");
}
__device__ __forceinline__ void cp_wait_all() {
    asm volatile("cp.async.wait_all;" ::: "memory");
}

// ---------------------------------------------------------------------------
__global__ void vq_reset_kernel() { g_acc = 0.0; }

// ---------------------------------------------------------------------------
// ||c||^2 per codebook row.
__global__ void vq_csq_kernel(const float* __restrict__ cb) {
    int row = blockIdx.x;
    float4 v = reinterpret_cast<const float4*>(cb + (size_t)row * DIM)[threadIdx.x];
    float s = v.x * v.x + v.y * v.y + v.z * v.z + v.w * v.w;
    #pragma unroll
    for (int o = 16; o > 0; o >>= 1) s += __shfl_xor_sync(0xffffffffu, s, o);
    __shared__ float ws[2];
    if ((threadIdx.x & 31) == 0) ws[threadIdx.x >> 5] = s;
    __syncthreads();
    if (threadIdx.x == 0) g_csq[row] = ws[0] + ws[1];
}

// ---------------------------------------------------------------------------
__device__ __forceinline__ void load_chunk(float* sCbuf, const float* __restrict__ cb,
                                           int cbase, int kbase, int tid) {
    #pragma unroll
    for (int r = 0; r < (BN * KCHUNK / 4) / THREADS; r++) {   // 8 iterations
        int t4   = tid + THREADS * r;        // 0..2047
        int code = t4 >> 3;                  // 8 float4 per 32-dim row
        int k4   = t4 & 7;
        const float* src = cb + (size_t)(cbase + code) * DIM + kbase + k4 * 4;
        cp_async16(sCbuf + code * SCP + k4 * 4, src);
    }
}

// ---------------------------------------------------------------------------
// Argmin over codes with packed f32x2 FMA. Block: 128 points, sweeps all K.
// Thread (ty = tid/16, tx = tid%16): points ty*8..ty*8+7 (4 pairs),
// codes tx + 16*j (j=0..15) per 256-code tile.
// score = ||c||^2 - 2*dot (x^2 constant per point, drops out of argmin).
__global__ __launch_bounds__(THREADS, 1)
void vq_argmin_kernel(const float* __restrict__ x, const float* __restrict__ cb) {
    extern __shared__ float smem[];
    float* sXt = smem;                       // [DIM][SXP] transposed X
    float* sC  = smem + DIM * SXP;           // [2][BN][SCP] C chunks

    const int tid = threadIdx.x;
    const int tx  = tid & 15;
    const int ty  = tid >> 4;
    const int pbase = blockIdx.x * BM;

    // Prefetch first C chunk immediately (overlaps with X transpose)
    load_chunk(sC, cb, 0, 0, tid);
    cp_commit();

    // X tile transposed into smem: sXt[dim][point]
    for (int t = tid; t < BM * D4; t += THREADS) {
        int p = t >> 6, c4 = t & 63;
        float4 v = reinterpret_cast<const float4*>(x)[(size_t)(pbase + p) * D4 + c4];
        int d = c4 * 4;
        sXt[(d + 0) * SXP + p] = v.x;
        sXt[(d + 1) * SXP + p] = v.y;
        sXt[(d + 2) * SXP + p] = v.z;
        sXt[(d + 3) * SXP + p] = v.w;
    }

    ull acc2[4][TN];
    #pragma unroll
    for (int ip = 0; ip < 4; ip++)
        #pragma unroll
        for (int j = 0; j < TN; j++) acc2[ip][j] = 0ull;

    float best[TM];
    int   bidx[TM];
    #pragma unroll
    for (int m = 0; m < TM; m++) { best[m] = FLT_MAX; bidx[m] = 0; }

    const ull NEG2 = pack2(-2.0f);
    int buf = 0;

    for (int tile = 0; tile < NTILE; tile++) {
        const int cbase = tile * BN;
        for (int ch = 0; ch < NCHUNK; ch++) {
            cp_wait_all();
            __syncthreads();   // chunk data visible; prev buf consumers done

            // prefetch next chunk into other buffer
            int nxt = tile * NCHUNK + ch + 1;
            if (nxt < NTILE * NCHUNK) {
                load_chunk(sC + (buf ^ 1) * BN * SCP, cb,
                           (nxt / NCHUNK) * BN, (nxt % NCHUNK) * KCHUNK, tid);
            }
            cp_commit();

            const float* sCc = sC + buf * BN * SCP;
            const int kbase = ch * KCHUNK;

            #pragma unroll
            for (int kc = 0; kc < KCHUNK / 4; kc++) {
                // x pairs for 4 dims: free packing via ulonglong2 LDS.128
                ull xp[4][4];
                #pragma unroll
                for (int kk = 0; kk < 4; kk++) {
                    const ulonglong2* px = reinterpret_cast<const ulonglong2*>(
                        &sXt[(kbase + kc * 4 + kk) * SXP + ty * TM]);
                    ulonglong2 v0 = px[0];
                    ulonglong2 v1 = px[1];
                    xp[kk][0] = v0.x; xp[kk][1] = v0.y;
                    xp[kk][2] = v1.x; xp[kk][3] = v1.y;
                }
                #pragma unroll
                for (int j = 0; j < TN; j++) {
                    float4 c = *reinterpret_cast<const float4*>(
                        &sCc[(tx + 16 * j) * SCP + kc * 4]);
                    ull cc0 = pack2(c.x);
                    #pragma unroll
                    for (int ip = 0; ip < 4; ip++) acc2[ip][j] = ffma2(xp[0][ip], cc0, acc2[ip][j]);
                    ull cc1 = pack2(c.y);
                    #pragma unroll
                    for (int ip = 0; ip < 4; ip++) acc2[ip][j] = ffma2(xp[1][ip], cc1, acc2[ip][j]);
                    ull cc2 = pack2(c.z);
                    #pragma unroll
                    for (int ip = 0; ip < 4; ip++) acc2[ip][j] = ffma2(xp[2][ip], cc2, acc2[ip][j]);
                    ull cc3 = pack2(c.w);
                    #pragma unroll
                    for (int ip = 0; ip < 4; ip++) acc2[ip][j] = ffma2(xp[3][ip], cc3, acc2[ip][j]);
                }
            }
            buf ^= 1;
        }

        // Tile epilogue: score = csq - 2*dot; j ascending => code index ascending,
        // strict < reproduces argmin first-min tie-break.
        #pragma unroll
        for (int j = 0; j < TN; j++) {
            int ci = cbase + tx + 16 * j;
            ull cs2 = pack2(__ldg(&g_csq[ci]));
            #pragma unroll
            for (int ip = 0; ip < 4; ip++) {
                float2 s = unpack2(ffma2(acc2[ip][j], NEG2, cs2));
                if (s.x < best[2 * ip])     { best[2 * ip] = s.x;     bidx[2 * ip] = ci; }
                if (s.y < best[2 * ip + 1]) { best[2 * ip + 1] = s.y; bidx[2 * ip + 1] = ci; }
                acc2[ip][j] = 0ull;
            }
        }
    }

    // Cross-thread (tx, 16 lanes) reduction; lowest index wins on exact ties.
    #pragma unroll
    for (int m = 0; m < TM; m++) {
        float s = best[m];
        int   ii = bidx[m];
        #pragma unroll
        for (int off = 8; off > 0; off >>= 1) {
            float so = __shfl_xor_sync(0xffffffffu, s, off);
            int   io = __shfl_xor_sync(0xffffffffu, ii, off);
            if (so < s || (so == s && io < ii)) { s = so; ii = io; }
        }
        if (tx == 0) g_idx[pbase + ty * TM + m] = ii;
    }
}

// ---------------------------------------------------------------------------
// Gather quantized rows, emit straight-through output x + (q - x),
// accumulate sum of (q-x)^2 into g_acc.
__global__ void vq_gather_kernel(const float* __restrict__ x,
                                 const float* __restrict__ cb,
                                 float* __restrict__ out) {
    const int total4 = N_POINTS * D4;
    float part = 0.f;
    for (int i4 = blockIdx.x * blockDim.x + threadIdx.x; i4 < total4;
         i4 += gridDim.x * blockDim.x) {
        int p  = i4 >> 6;
        int c4 = i4 & 63;
        int ci = g_idx[p];
        float4 xv = reinterpret_cast<const float4*>(x)[i4];
        float4 qv = reinterpret_cast<const float4*>(cb)[(size_t)ci * D4 + c4];
        float4 d, o;
        d.x = qv.x - xv.x; d.y = qv.y - xv.y; d.z = qv.z - xv.z; d.w = qv.w - xv.w;
        o.x = xv.x + d.x;  o.y = xv.y + d.y;  o.z = xv.z + d.z;  o.w = xv.w + d.w;
        reinterpret_cast<float4*>(out)[i4] = o;
        part += d.x * d.x + d.y * d.y + d.z * d.z + d.w * d.w;
    }
    #pragma unroll
    for (int o = 16; o > 0; o >>= 1) part += __shfl_xor_sync(0xffffffffu, part, o);
    __shared__ float ws[8];
    if ((threadIdx.x & 31) == 0) ws[threadIdx.x >> 5] = part;
    __syncthreads();
    if (threadIdx.x == 0) {
        float bs = 0.f;
        for (int w = 0; w < (int)(blockDim.x >> 5); w++) bs += ws[w];
        atomicAdd(&g_acc, (double)bs);
    }
}

// ---------------------------------------------------------------------------
__global__ void vq_finalize_kernel(float* __restrict__ out) {
    out[(size_t)N_POINTS * DIM] = (float)(1.25 * g_acc / (double)(N_POINTS * DIM));
}

// ---------------------------------------------------------------------------
extern "C" void kernel_launch(void* const* d_in, const int* in_sizes, int n_in,
                              void* d_out, int out_size) {
    const float* x  = (const float*)d_in[0];
    const float* cb = (const float*)d_in[1];
    float* out = (float*)d_out;

    (void)in_sizes; (void)n_in; (void)out_size;

    static bool attr_set = false;
    size_t smem_bytes = (size_t)(DIM * SXP + 2 * BN * SCP) * sizeof(float); // ~204 KB
    if (!attr_set) {
        cudaFuncSetAttribute(vq_argmin_kernel,
                             cudaFuncAttributeMaxDynamicSharedMemorySize,
                             (int)smem_bytes);
        attr_set = true;
    }

    vq_reset_kernel<<<1, 1>>>();
    vq_csq_kernel<<<K_CODES, 64>>>(cb);
    vq_argmin_kernel<<<N_POINTS / BM, THREADS, smem_bytes>>>(x, cb);
    vq_gather_kernel<<<2048, 256>>>(x, cb, out);
    vq_finalize_kernel<<<1, 1>>>(out);
}

// round 4
// speedup vs baseline: 1.9423x; 1.2351x over previous
#include <cuda_runtime.h>
#include <cuda_bf16.h>
#include <cfloat>
#include <cstdint>

#define N_POINTS 32768
#define DIM      256
#define D4       (DIM / 4)
#define K_CODES  4096
#define BM       128
#define BN       128
#define NTILE    (K_CODES / BN)       // 32
#define THREADS  256
#define CAND     16
#define MARGIN   4e-3f

// smem byte offsets (dynamic base is 1024-aligned already for extern shared)
#define SM_CSQ  0                      // 4096 f32 = 16 KB
#define SM_A    16384                  // A hi 64 KB + A lo 64 KB
#define SM_ALO  (SM_A + 65536)
#define SM_B    (SM_A + 131072)        // 2 x (hi 16 KB + lo 16 KB) = 64 KB
#define SMEM_DYN (SM_B + 65536)        // 212992 B

typedef unsigned int uint32;

// ---------------------------------------------------------------------------
// Device scratch (static — no allocations allowed)
__device__ float  g_csq[K_CODES];
__device__ int    g_idx[N_POINTS];
__device__ double g_acc;
__device__ int    g_nflag;
__device__ int    g_flag[N_POINTS];
__device__ unsigned short g_cand[N_POINTS * 4 * CAND];
__device__ unsigned char  g_ccnt[N_POINTS * 4];
__device__ __align__(128) __nv_bfloat16 g_cbhi[K_CODES * DIM];
__device__ __align__(128) __nv_bfloat16 g_cblo[K_CODES * DIM];

// ---------------------------------------------------------------------------
__device__ __forceinline__ uint32 smem_u32(const void* p) {
    return (uint32)__cvta_generic_to_shared(p);
}
__device__ __forceinline__ void cp_async16(uint32 dst, const void* src) {
    asm volatile("cp.async.cg.shared.global [%0], [%1], 16;" :: "r"(dst), "l"(src));
}
#define CP_COMMIT()  asm volatile("cp.async.commit_group;" ::: "memory")
#define CP_WAIT(n)   asm volatile("cp.async.wait_group %0;" :: "n"(n) : "memory")

__device__ __forceinline__ void ldsm4(uint32* r, uint32 addr) {
    asm volatile("ldmatrix.sync.aligned.m8n8.x4.shared.b16 {%0,%1,%2,%3}, [%4];"
                 : "=r"(r[0]), "=r"(r[1]), "=r"(r[2]), "=r"(r[3]) : "r"(addr));
}
__device__ __forceinline__ void mma16816(float* d, const uint32* a, const uint32* b) {
    asm volatile("mma.sync.aligned.m16n8k16.row.col.f32.bf16.bf16.f32 "
                 "{%0,%1,%2,%3}, {%4,%5,%6,%7}, {%8,%9}, {%0,%1,%2,%3};"
                 : "+f"(d[0]), "+f"(d[1]), "+f"(d[2]), "+f"(d[3])
                 : "r"(a[0]), "r"(a[1]), "r"(a[2]), "r"(a[3]), "r"(b[0]), "r"(b[1]));
}

// ---------------------------------------------------------------------------
__global__ void vq_reset_kernel() { g_acc = 0.0; g_nflag = 0; }

// ---------------------------------------------------------------------------
__global__ void vq_csq_kernel(const float* __restrict__ cb) {
    int row = blockIdx.x;
    float4 v = reinterpret_cast<const float4*>(cb + (size_t)row * DIM)[threadIdx.x];
    float s = v.x * v.x + v.y * v.y + v.z * v.z + v.w * v.w;
    #pragma unroll
    for (int o = 16; o > 0; o >>= 1) s += __shfl_xor_sync(0xffffffffu, s, o);
    __shared__ float ws[2];
    if ((threadIdx.x & 31) == 0) ws[threadIdx.x >> 5] = s;
    __syncthreads();
    if (threadIdx.x == 0) g_csq[row] = ws[0] + ws[1];
}

// ---------------------------------------------------------------------------
// Split codebook into bf16 hi/lo, row-major.
__global__ void vq_cbsplit_kernel(const float* __restrict__ cb) {
    for (int e = blockIdx.x * blockDim.x + threadIdx.x; e < K_CODES * DIM;
         e += gridDim.x * blockDim.x) {
        float c = cb[e];
        __nv_bfloat16 h = __float2bfloat16_rn(c);
        __nv_bfloat16 l = __float2bfloat16_rn(c - __bfloat162float(h));
        g_cbhi[e] = h;
        g_cblo[e] = l;
    }
}

// ---------------------------------------------------------------------------
// Load one B chunk (tile of 128 codes, 64 dims, hi+lo) into smem buffer `buf`.
// Swizzle: 16B segment s of code row goes to code*128 + ((s*16) ^ ((code&7)<<4)).
__device__ __forceinline__ void load_chunk(uint32 smB, int iter, int tid) {
    const int tile = iter >> 2, kc = iter & 3, buf = iter & 1;
    const uint32 dHi = smB + buf * 32768;
    const uint32 dLo = dHi + 16384;
    const __nv_bfloat16* sHi = g_cbhi + (size_t)tile * BN * DIM + kc * 64;
    const __nv_bfloat16* sLo = g_cblo + (size_t)tile * BN * DIM + kc * 64;
    #pragma unroll
    for (int r = 0; r < 4; r++) {
        int idx  = tid + r * THREADS;        // 0..1023
        int code = idx >> 3, seg = idx & 7;
        uint32 off = code * 128 + ((seg * 16) ^ ((code & 7) << 4));
        cp_async16(dHi + off, sHi + (size_t)code * DIM + seg * 8);
        cp_async16(dLo + off, sLo + (size_t)code * DIM + seg * 8);
    }
}

// ---------------------------------------------------------------------------
// Tensor-core (mma.sync) argmin with error-bounded candidate tracking.
__global__ __launch_bounds__(THREADS, 1)
void vq_mma_kernel(const float* __restrict__ x) {
    extern __shared__ unsigned char smb[];
    const uint32 sbase = smem_u32(smb);
    float* sCsq = reinterpret_cast<float*>(smb + SM_CSQ);

    const int tid   = threadIdx.x;
    const int lane  = tid & 31;
    const int warp  = tid >> 5;
    const int warpM = warp * 16;
    const int pbase = blockIdx.x * BM;

    // Pipeline prologue: start chunk 0
    load_chunk(sbase + SM_B, 0, tid);
    CP_COMMIT();

    // csq -> smem
    for (int i = tid; i < K_CODES; i += THREADS) sCsq[i] = g_csq[i];

    // A tile: 128 pts x 256 dims -> bf16 hi/lo, swizzled rows of 512 B
    {
        const float4* xg = reinterpret_cast<const float4*>(x + (size_t)pbase * DIM);
        #pragma unroll
        for (int i = 0; i < 16; i++) {
            int idx = tid + i * THREADS;     // (row, seg8): 128*32 = 4096
            int row = idx >> 5, seg = idx & 31;
            float4 v0 = xg[row * 64 + seg * 2];
            float4 v1 = xg[row * 64 + seg * 2 + 1];
            float f[8] = {v0.x, v0.y, v0.z, v0.w, v1.x, v1.y, v1.z, v1.w};
            __nv_bfloat16 h[8], l[8];
            #pragma unroll
            for (int j = 0; j < 8; j++) {
                h[j] = __float2bfloat16_rn(f[j]);
                l[j] = __float2bfloat16_rn(f[j] - __bfloat162float(h[j]));
            }
            uint32 off = row * 512 + ((seg * 16) ^ ((row & 7) << 4));
            *reinterpret_cast<uint4*>(smb + SM_A   + off) = *reinterpret_cast<uint4*>(h);
            *reinterpret_cast<uint4*>(smb + SM_ALO + off) = *reinterpret_cast<uint4*>(l);
        }
    }

    // Per-thread fragment addressing constants
    const uint32 a_row   = warpM + (lane & 7) + ((lane >> 3) & 1) * 8;
    const uint32 a_k16   = ((lane >> 4) & 1) * 16;
    const uint32 swz     = (lane & 7) << 4;          // == (a_row&7)<<4 == (b_code&7)<<4
    const uint32 aHiBase = sbase + SM_A   + a_row * 512;
    const uint32 aLoBase = sbase + SM_ALO + a_row * 512;
    const uint32 b_cloc  = ((lane >> 4) & 1) * 8 + (lane & 7);
    const uint32 b_k16   = ((lane >> 3) & 1) * 16;

    float dacc[16][4];
    #pragma unroll
    for (int nf = 0; nf < 16; nf++)
        #pragma unroll
        for (int q = 0; q < 4; q++) dacc[nf][q] = 0.f;

    // Per-thread argmin state for its 2 rows (lane/4 and lane/4+8)
    float best[2] = {FLT_MAX, FLT_MAX}, sec[2] = {FLT_MAX, FLT_MAX};
    int   bidx[2] = {0, 0};
    int   ccnt[2] = {0, 0};
    int   ovf [2] = {0, 0};
    unsigned short cbuf[2][CAND];

    __syncthreads();   // A + csq visible (cp.async of chunk0 still in flight)

    for (int it = 0; it < NTILE * 4; it++) {
        const int tile = it >> 2, kc = it & 3, buf = it & 1;
        __syncthreads();                       // everyone done reading buf we refill
        if (it + 1 < NTILE * 4) load_chunk(sbase + SM_B, it + 1, tid);
        CP_COMMIT();
        CP_WAIT(1);                            // chunk `it` resident
        __syncthreads();

        const uint32 bHi = sbase + SM_B + buf * 32768;
        const uint32 bLo = bHi + 16384;

        #pragma unroll
        for (int ks = 0; ks < 4; ks++) {
            uint32 ah[4], al[4];
            uint32 aoff = ((uint32)(kc * 128 + ks * 32) + a_k16) ^ swz;
            ldsm4(ah, aHiBase + aoff);
            ldsm4(al, aLoBase + aoff);
            uint32 boff = ((uint32)(ks * 32) + b_k16) ^ swz;
            #pragma unroll
            for (int np = 0; np < 8; np++) {
                uint32 bh[4], bl[4];
                uint32 baddr = (np * 16 + b_cloc) * 128 + boff;
                ldsm4(bh, bHi + baddr);
                ldsm4(bl, bLo + baddr);
                mma16816(dacc[2 * np],     ah, bh);
                mma16816(dacc[2 * np],     ah, bl);
                mma16816(dacc[2 * np],     al, bh);
                mma16816(dacc[2 * np + 1], ah, bh + 2);
                mma16816(dacc[2 * np + 1], ah, bl + 2);
                mma16816(dacc[2 * np + 1], al, bh + 2);
            }
        }

        if (kc == 3) {
            // Epilogue for this 128-code tile: score = csq - 2*dot
            const int cib = tile * BN + (lane & 3) * 2;
            #pragma unroll
            for (int nf = 0; nf < 16; nf++) {
                const int ci0 = cib + nf * 8;
                const float cs0 = sCsq[ci0], cs1 = sCsq[ci0 + 1];
                #pragma unroll
                for (int q = 0; q < 2; q++) {
                    float s0 = fmaf(-2.f, dacc[nf][2 * q],     cs0);
                    float s1 = fmaf(-2.f, dacc[nf][2 * q + 1], cs1);
                    if (s0 < best[q]) { sec[q] = best[q]; best[q] = s0; bidx[q] = ci0; }
                    else if (s0 < sec[q]) sec[q] = s0;
                    if (s0 <= best[q] + MARGIN) {
                        if (ccnt[q] < CAND) cbuf[q][ccnt[q]++] = (unsigned short)ci0;
                        else ovf[q] = 1;
                    }
                    if (s1 < best[q]) { sec[q] = best[q]; best[q] = s1; bidx[q] = ci0 + 1; }
                    else if (s1 < sec[q]) sec[q] = s1;
                    if (s1 <= best[q] + MARGIN) {
                        if (ccnt[q] < CAND) cbuf[q][ccnt[q]++] = (unsigned short)(ci0 + 1);
                        else ovf[q] = 1;
                    }
                    dacc[nf][2 * q] = 0.f; dacc[nf][2 * q + 1] = 0.f;
                }
            }
        }
    }

    // Dump per-lane candidate lists, then merge the 4 quad lanes per point.
    #pragma unroll
    for (int q = 0; q < 2; q++) {
        const int pg = pbase + warpM + (lane >> 2) + q * 8;
        const int slot = pg * 4 + (lane & 3);
        g_ccnt[slot] = (unsigned char)(ccnt[q] | (ovf[q] ? 0x80 : 0));
        for (int j = 0; j < ccnt[q]; j++) g_cand[(size_t)slot * CAND + j] = cbuf[q][j];

        float b = best[q], s = sec[q];
        int   i = bidx[q], o = ovf[q];
        #pragma unroll
        for (int off = 1; off <= 2; off <<= 1) {
            float ob = __shfl_xor_sync(0xffffffffu, b, off);
            float os = __shfl_xor_sync(0xffffffffu, s, off);
            int   oi = __shfl_xor_sync(0xffffffffu, i, off);
            int   oo = __shfl_xor_sync(0xffffffffu, o, off);
            if (ob < b || (ob == b && oi < i)) {
                s = fminf(fminf(b, s), os); b = ob; i = oi;
            } else {
                s = fminf(fminf(ob, s), os);
            }
            o |= oo;
        }
        if ((lane & 3) == 0) {
            if (o || (s - b) <= MARGIN) {
                int pos = atomicAdd(&g_nflag, 1);
                g_flag[pos] = pg;
            } else {
                g_idx[pg] = i;
            }
        }
    }
}

// ---------------------------------------------------------------------------
// Exact fp32 resolution for flagged points.
__global__ void vq_cleanup_kernel(const float* __restrict__ x,
                                  const float* __restrict__ cb) {
    __shared__ float sx[DIM];
    __shared__ float rs[256];
    __shared__ int   ri[256];
    __shared__ unsigned short cl[4 * CAND];
    __shared__ int scnt[2];
    const int tid = threadIdx.x;
    const int nf = g_nflag;
    for (int f = blockIdx.x; f < nf; f += gridDim.x) {
        int p = g_flag[f];
        for (int i = tid; i < DIM; i += 256) sx[i] = x[(size_t)p * DIM + i];
        if (tid == 0) {
            int tot = 0, anyovf = 0;
            for (int j = 0; j < 4; j++) {
                int c = g_ccnt[p * 4 + j];
                anyovf |= (c & 0x80);
                c &= 0x7f;
                for (int k = 0; k < c; k++)
                    cl[tot + k] = g_cand[(size_t)(p * 4 + j) * CAND + k];
                tot += c;
            }
            scnt[0] = tot; scnt[1] = anyovf;
        }
        __syncthreads();
        const int tot = scnt[0], anyovf = scnt[1];
        float bs = FLT_MAX;
        int   bi = 0x7fffffff;
        const float4* sx4 = reinterpret_cast<const float4*>(sx);
        if (!anyovf) {
            if (tid < tot) {
                int ci = (int)cl[tid];
                const float4* cr = reinterpret_cast<const float4*>(cb + (size_t)ci * DIM);
                float dot = 0.f;
                #pragma unroll 16
                for (int k = 0; k < D4; k++) {
                    float4 cv = cr[k], xv = sx4[k];
                    dot = fmaf(xv.x, cv.x, dot); dot = fmaf(xv.y, cv.y, dot);
                    dot = fmaf(xv.z, cv.z, dot); dot = fmaf(xv.w, cv.w, dot);
                }
                bs = fmaf(-2.f, dot, g_csq[ci]);
                bi = ci;
            }
        } else {
            for (int ci = tid; ci < K_CODES; ci += 256) {
                const float4* cr = reinterpret_cast<const float4*>(cb + (size_t)ci * DIM);
                float dot = 0.f;
                #pragma unroll 16
                for (int k = 0; k < D4; k++) {
                    float4 cv = cr[k], xv = sx4[k];
                    dot = fmaf(xv.x, cv.x, dot); dot = fmaf(xv.y, cv.y, dot);
                    dot = fmaf(xv.z, cv.z, dot); dot = fmaf(xv.w, cv.w, dot);
                }
                float s = fmaf(-2.f, dot, g_csq[ci]);
                if (s < bs) { bs = s; bi = ci; }
            }
        }
        rs[tid] = bs; ri[tid] = bi;
        __syncthreads();
        for (int o = 128; o > 0; o >>= 1) {
            if (tid < o) {
                if (rs[tid + o] < rs[tid] ||
                    (rs[tid + o] == rs[tid] && ri[tid + o] < ri[tid])) {
                    rs[tid] = rs[tid + o]; ri[tid] = ri[tid + o];
                }
            }
            __syncthreads();
        }
        if (tid == 0) g_idx[p] = ri[0];
        __syncthreads();
    }
}

// ---------------------------------------------------------------------------
__global__ void vq_gather_kernel(const float* __restrict__ x,
                                 const float* __restrict__ cb,
                                 float* __restrict__ out) {
    const int total4 = N_POINTS * D4;
    float part = 0.f;
    for (int i4 = blockIdx.x * blockDim.x + threadIdx.x; i4 < total4;
         i4 += gridDim.x * blockDim.x) {
        int p  = i4 >> 6;
        int c4 = i4 & 63;
        int ci = g_idx[p];
        float4 xv = reinterpret_cast<const float4*>(x)[i4];
        float4 qv = reinterpret_cast<const float4*>(cb)[(size_t)ci * D4 + c4];
        float4 d, o;
        d.x = qv.x - xv.x; d.y = qv.y - xv.y; d.z = qv.z - xv.z; d.w = qv.w - xv.w;
        o.x = xv.x + d.x;  o.y = xv.y + d.y;  o.z = xv.z + d.z;  o.w = xv.w + d.w;
        reinterpret_cast<float4*>(out)[i4] = o;
        part += d.x * d.x + d.y * d.y + d.z * d.z + d.w * d.w;
    }
    #pragma unroll
    for (int o = 16; o > 0; o >>= 1) part += __shfl_xor_sync(0xffffffffu, part, o);
    __shared__ float ws[8];
    if ((threadIdx.x & 31) == 0) ws[threadIdx.x >> 5] = part;
    __syncthreads();
    if (threadIdx.x == 0) {
        float bs = 0.f;
        for (int w = 0; w < (int)(blockDim.x >> 5); w++) bs += ws[w];
        atomicAdd(&g_acc, (double)bs);
    }
}

// ---------------------------------------------------------------------------
__global__ void vq_finalize_kernel(float* __restrict__ out) {
    out[(size_t)N_POINTS * DIM] = (float)(1.25 * g_acc / (double)(N_POINTS * DIM));
}

// ---------------------------------------------------------------------------
extern "C" void kernel_launch(void* const* d_in, const int* in_sizes, int n_in,
                              void* d_out, int out_size) {
    const float* x  = (const float*)d_in[0];
    const float* cb = (const float*)d_in[1];
    float* out = (float*)d_out;
    (void)in_sizes; (void)n_in; (void)out_size;

    cudaFuncSetAttribute(vq_mma_kernel, cudaFuncAttributeMaxDynamicSharedMemorySize,
                         SMEM_DYN);

    vq_reset_kernel<<<1, 1>>>();
    vq_csq_kernel<<<K_CODES, 64>>>(cb);
    vq_cbsplit_kernel<<<1024, 256>>>(cb);
    vq_mma_kernel<<<N_POINTS / BM, THREADS, SMEM_DYN>>>(x);
    vq_cleanup_kernel<<<256, 256>>>(x, cb);
    vq_gather_kernel<<<2048, 256>>>(x, cb, out);
    vq_finalize_kernel<<<1, 1>>>(out);
}

// round 6
// speedup vs baseline: 2.8373x; 1.4608x over previous
#include <cuda_runtime.h>
#include <cuda_fp16.h>
#include <cfloat>
#include <cstdint>

#define N_POINTS 32768
#define DIM      256
#define D4       (DIM / 4)
#define K_CODES  4096
#define BM       128
#define BN       128
#define NTILE    (K_CODES / BN)       // 32
#define THREADS  256
#define MARGIN   6e-3f

// smem layout (bytes from dynamic base)
#define SM_CSQ  0                      // 4096 f32 = 16 KB
#define SM_A    16384                  // 128 rows x 512 B (fp16) = 64 KB
#define SM_B    81920                  // 2 x 16 KB chunk buffers
#define SMEM_DYN 114688                // 112 KB -> 2 CTAs/SM

typedef unsigned int uint32;

// ---------------------------------------------------------------------------
// Device scratch (static — no allocations allowed)
__device__ float  g_csq[K_CODES];
__device__ int    g_idx[N_POINTS];
__device__ double g_acc;
__device__ int    g_nflag;
__device__ int    g_flag[N_POINTS];
__device__ __align__(128) __half g_cbh[K_CODES * DIM];

// ---------------------------------------------------------------------------
__device__ __forceinline__ uint32 smem_u32(const void* p) {
    return (uint32)__cvta_generic_to_shared(p);
}
__device__ __forceinline__ void cp_async16(uint32 dst, const void* src) {
    asm volatile("cp.async.cg.shared.global [%0], [%1], 16;" :: "r"(dst), "l"(src));
}
#define CP_COMMIT()  asm volatile("cp.async.commit_group;" ::: "memory")
#define CP_WAIT(n)   asm volatile("cp.async.wait_group %0;" :: "n"(n) : "memory")

__device__ __forceinline__ void ldsm4(uint32* r, uint32 addr) {
    asm volatile("ldmatrix.sync.aligned.m8n8.x4.shared.b16 {%0,%1,%2,%3}, [%4];"
                 : "=r"(r[0]), "=r"(r[1]), "=r"(r[2]), "=r"(r[3]) : "r"(addr));
}
__device__ __forceinline__ void mma16816(float* d, const uint32* a, const uint32* b) {
    asm volatile("mma.sync.aligned.m16n8k16.row.col.f32.f16.f16.f32 "
                 "{%0,%1,%2,%3}, {%4,%5,%6,%7}, {%8,%9}, {%0,%1,%2,%3};"
                 : "+f"(d[0]), "+f"(d[1]), "+f"(d[2]), "+f"(d[3])
                 : "r"(a[0]), "r"(a[1]), "r"(a[2]), "r"(a[3]), "r"(b[0]), "r"(b[1]));
}

// ---------------------------------------------------------------------------
__global__ void vq_reset_kernel() { g_acc = 0.0; g_nflag = 0; }

// ---------------------------------------------------------------------------
__global__ void vq_csq_kernel(const float* __restrict__ cb) {
    int row = blockIdx.x;
    float4 v = reinterpret_cast<const float4*>(cb + (size_t)row * DIM)[threadIdx.x];
    float s = v.x * v.x + v.y * v.y + v.z * v.z + v.w * v.w;
    #pragma unroll
    for (int o = 16; o > 0; o >>= 1) s += __shfl_xor_sync(0xffffffffu, s, o);
    __shared__ float ws[2];
    if ((threadIdx.x & 31) == 0) ws[threadIdx.x >> 5] = s;
    __syncthreads();
    if (threadIdx.x == 0) g_csq[row] = ws[0] + ws[1];
}

// ---------------------------------------------------------------------------
__global__ void vq_cbhalf_kernel(const float* __restrict__ cb) {
    for (int e = blockIdx.x * blockDim.x + threadIdx.x; e < K_CODES * DIM;
         e += gridDim.x * blockDim.x)
        g_cbh[e] = __float2half_rn(cb[e]);
}

// ---------------------------------------------------------------------------
// Stream one B chunk: 128 codes x 64 dims fp16 = 16 KB, swizzled rows of 128 B.
__device__ __forceinline__ void load_chunk(uint32 smB, int it, int tid) {
    const int tile = it >> 2, kc = it & 3, buf = it & 1;
    const uint32 dst = smB + buf * 16384;
    const __half* src = g_cbh + (size_t)tile * BN * DIM + kc * 64;
    #pragma unroll
    for (int r = 0; r < 4; r++) {
        int idx  = tid + r * THREADS;        // 0..1023
        int code = idx >> 3, seg = idx & 7;
        uint32 off = code * 128 + ((seg * 16) ^ ((code & 7) << 4));
        cp_async16(dst + off, src + (size_t)code * DIM + seg * 8);
    }
}

// ---------------------------------------------------------------------------
// 1-pass fp16 tensor-core argmin, warp tile m32 x n64, 2 CTAs/SM.
__global__ __launch_bounds__(THREADS, 2)
void vq_mma_kernel(const float* __restrict__ x) {
    extern __shared__ unsigned char smb[];
    const uint32 sbase = smem_u32(smb);
    float* sCsq = reinterpret_cast<float*>(smb + SM_CSQ);

    const int tid  = threadIdx.x;
    const int lane = tid & 31;
    const int warp = tid >> 5;
    const int wm   = warp >> 1;          // 0..3 -> rows wm*32..+31
    const int wn   = warp & 1;           // 0..1 -> codes wn*64..+63 in tile
    const int pbase = blockIdx.x * BM;

    load_chunk(sbase + SM_B, 0, tid);
    CP_COMMIT();

    for (int i = tid; i < K_CODES; i += THREADS) sCsq[i] = g_csq[i];

    // A tile: 128 pts x 256 dims -> fp16, swizzled rows of 512 B
    {
        const float4* xg = reinterpret_cast<const float4*>(x + (size_t)pbase * DIM);
        #pragma unroll
        for (int i = 0; i < 16; i++) {
            int idx = tid + i * THREADS;     // (row, seg16B): 128*32
            int row = idx >> 5, seg = idx & 31;
            float4 v0 = xg[row * 64 + seg * 2];
            float4 v1 = xg[row * 64 + seg * 2 + 1];
            __half h[8];
            h[0] = __float2half_rn(v0.x); h[1] = __float2half_rn(v0.y);
            h[2] = __float2half_rn(v0.z); h[3] = __float2half_rn(v0.w);
            h[4] = __float2half_rn(v1.x); h[5] = __float2half_rn(v1.y);
            h[6] = __float2half_rn(v1.z); h[7] = __float2half_rn(v1.w);
            uint32 off = row * 512 + ((seg * 16) ^ ((row & 7) << 4));
            *reinterpret_cast<uint4*>(smb + SM_A + off) = *reinterpret_cast<uint4*>(h);
        }
    }

    // Fragment addressing
    const uint32 a_row  = wm * 32 + (lane & 7) + ((lane >> 3) & 1) * 8;
    const uint32 a_k16  = ((lane >> 4) & 1) * 16;
    const uint32 swz    = (lane & 7) << 4;
    const uint32 aBase0 = sbase + SM_A + a_row * 512;          // mi=0
    const uint32 aBase1 = aBase0 + 16 * 512;                    // mi=1
    const uint32 b_cloc = ((lane >> 4) & 1) * 8 + (lane & 7);
    const uint32 b_k16  = ((lane >> 3) & 1) * 16;

    float dacc[2][8][4];
    #pragma unroll
    for (int mi = 0; mi < 2; mi++)
        #pragma unroll
        for (int nf = 0; nf < 8; nf++)
            #pragma unroll
            for (int q = 0; q < 4; q++) dacc[mi][nf][q] = 0.f;

    // Per-thread argmin state: 4 row-slots (mi,q)
    float best[4] = {FLT_MAX, FLT_MAX, FLT_MAX, FLT_MAX};
    float sec [4] = {FLT_MAX, FLT_MAX, FLT_MAX, FLT_MAX};
    int   bidx[4] = {0, 0, 0, 0};

    __syncthreads();

    for (int it = 0; it < NTILE * 4; it++) {
        const int tile = it >> 2, kc = it & 3, buf = it & 1;
        __syncthreads();                       // prior reads of buf^1 done
        if (it + 1 < NTILE * 4) load_chunk(sbase + SM_B, it + 1, tid);
        CP_COMMIT();
        CP_WAIT(1);                            // chunk `it` resident
        __syncthreads();

        const uint32 bBase = sbase + SM_B + buf * 16384;

        #pragma unroll
        for (int ks = 0; ks < 4; ks++) {
            uint32 a0[4], a1[4];
            uint32 aoff = ((uint32)(kc * 128 + ks * 32) + a_k16) ^ swz;
            ldsm4(a0, aBase0 + aoff);
            ldsm4(a1, aBase1 + aoff);
            uint32 boff = ((uint32)(ks * 32) + b_k16) ^ swz;
            #pragma unroll
            for (int np = 0; np < 4; np++) {
                uint32 bh[4];
                // NOTE: wn*64 code offset — this was the round-5 bug.
                ldsm4(bh, bBase + (uint32)(wn * 64 + np * 16 + b_cloc) * 128 + boff);
                mma16816(dacc[0][2 * np],     a0, bh);
                mma16816(dacc[1][2 * np],     a1, bh);
                mma16816(dacc[0][2 * np + 1], a0, bh + 2);
                mma16816(dacc[1][2 * np + 1], a1, bh + 2);
            }
        }

        if (kc == 3) {
            const int cb0 = tile * BN + wn * 64 + (lane & 3) * 2;
            #pragma unroll
            for (int nf = 0; nf < 8; nf++) {
                const int ci0 = cb0 + nf * 8;
                const float cs0 = sCsq[ci0], cs1 = sCsq[ci0 + 1];
                #pragma unroll
                for (int mi = 0; mi < 2; mi++)
                    #pragma unroll
                    for (int q = 0; q < 2; q++) {
                        const int k = mi * 2 + q;
                        float s0 = fmaf(-2.f, dacc[mi][nf][2 * q],     cs0);
                        float s1 = fmaf(-2.f, dacc[mi][nf][2 * q + 1], cs1);
                        if (s0 < best[k]) { sec[k] = best[k]; best[k] = s0; bidx[k] = ci0; }
                        else if (s0 < sec[k]) sec[k] = s0;
                        if (s1 < best[k]) { sec[k] = best[k]; best[k] = s1; bidx[k] = ci0 + 1; }
                        else if (s1 < sec[k]) sec[k] = s1;
                        dacc[mi][nf][2 * q] = 0.f; dacc[mi][nf][2 * q + 1] = 0.f;
                    }
            }
        }
    }

    // Quad-lane merge (lanes differing in lane&3 hold different codes, same rows)
    float mb[4], ms[4];
    int   mi_[4];
    #pragma unroll
    for (int k = 0; k < 4; k++) {
        float b = best[k], s = sec[k];
        int   i = bidx[k];
        #pragma unroll
        for (int off = 1; off <= 2; off <<= 1) {
            float ob = __shfl_xor_sync(0xffffffffu, b, off);
            float os = __shfl_xor_sync(0xffffffffu, s, off);
            int   oi = __shfl_xor_sync(0xffffffffu, i, off);
            if (ob < b)      { s = fminf(b, os); b = ob; i = oi; }
            else if (b < ob) { s = fminf(s, ob); }
            else             { s = b; i = min(i, oi); }
        }
        mb[k] = b; ms[k] = s; mi_[k] = i;
    }

    // Cross-warp-column merge via smem (reuse B region)
    float* mB = reinterpret_cast<float*>(smb + SM_B);     // [2][128]
    float* mS = mB + 256;
    int*   mI = reinterpret_cast<int*>(mS + 256);
    __syncthreads();
    if ((lane & 3) == 0) {
        #pragma unroll
        for (int k = 0; k < 4; k++) {
            int row = wm * 32 + (k >> 1) * 16 + (lane >> 2) + (k & 1) * 8;
            int s2  = wn * 128 + row;
            mB[s2] = mb[k]; mS[s2] = ms[k]; mI[s2] = mi_[k];
        }
    }
    __syncthreads();
    if (tid < BM) {
        float b0 = mB[tid], s0 = mS[tid], b1 = mB[128 + tid], s1 = mS[128 + tid];
        int   i0 = mI[tid], i1 = mI[128 + tid];
        float b, s; int i;
        if (b0 < b1)      { b = b0; i = i0; s = fminf(s0, b1); }
        else if (b1 < b0) { b = b1; i = i1; s = fminf(s1, b0); }
        else              { b = b0; i = min(i0, i1); s = b0; }
        const int pg = pbase + tid;
        if (s - b <= MARGIN) {
            int pos = atomicAdd(&g_nflag, 1);
            g_flag[pos] = pg;
        } else {
            g_idx[pg] = i;
        }
    }
}

// ---------------------------------------------------------------------------
// Exact fp32 full scan for flagged points (one block per point, grid-stride).
__global__ void vq_cleanup_kernel(const float* __restrict__ x,
                                  const float* __restrict__ cb) {
    __shared__ float sx[DIM];
    __shared__ float rs[256];
    __shared__ int   ri[256];
    const int tid = threadIdx.x;
    const int nf = g_nflag;
    for (int f = blockIdx.x; f < nf; f += gridDim.x) {
        int p = g_flag[f];
        __syncthreads();
        for (int i = tid; i < DIM; i += 256) sx[i] = x[(size_t)p * DIM + i];
        __syncthreads();
        const float4* sx4 = reinterpret_cast<const float4*>(sx);
        float bs = FLT_MAX;
        int   bi = 0x7fffffff;
        for (int ci = tid; ci < K_CODES; ci += 256) {
            const float4* cr = reinterpret_cast<const float4*>(cb + (size_t)ci * DIM);
            float dot = 0.f;
            #pragma unroll 16
            for (int k = 0; k < D4; k++) {
                float4 cv = cr[k], xv = sx4[k];
                dot = fmaf(xv.x, cv.x, dot); dot = fmaf(xv.y, cv.y, dot);
                dot = fmaf(xv.z, cv.z, dot); dot = fmaf(xv.w, cv.w, dot);
            }
            float s = fmaf(-2.f, dot, g_csq[ci]);
            if (s < bs) { bs = s; bi = ci; }       // ascending ci: strict <
        }
        rs[tid] = bs; ri[tid] = bi;
        __syncthreads();
        for (int o = 128; o > 0; o >>= 1) {
            if (tid < o) {
                if (rs[tid + o] < rs[tid] ||
                    (rs[tid + o] == rs[tid] && ri[tid + o] < ri[tid])) {
                    rs[tid] = rs[tid + o]; ri[tid] = ri[tid + o];
                }
            }
            __syncthreads();
        }
        if (tid == 0) g_idx[p] = ri[0];
    }
}

// ---------------------------------------------------------------------------
__global__ void vq_gather_kernel(const float* __restrict__ x,
                                 const float* __restrict__ cb,
                                 float* __restrict__ out) {
    const int total4 = N_POINTS * D4;
    float part = 0.f;
    for (int i4 = blockIdx.x * blockDim.x + threadIdx.x; i4 < total4;
         i4 += gridDim.x * blockDim.x) {
        int p  = i4 >> 6;
        int c4 = i4 & 63;
        int ci = g_idx[p];
        float4 xv = reinterpret_cast<const float4*>(x)[i4];
        float4 qv = reinterpret_cast<const float4*>(cb)[(size_t)ci * D4 + c4];
        float4 d, o;
        d.x = qv.x - xv.x; d.y = qv.y - xv.y; d.z = qv.z - xv.z; d.w = qv.w - xv.w;
        o.x = xv.x + d.x;  o.y = xv.y + d.y;  o.z = xv.z + d.z;  o.w = xv.w + d.w;
        reinterpret_cast<float4*>(out)[i4] = o;
        part += d.x * d.x + d.y * d.y + d.z * d.z + d.w * d.w;
    }
    #pragma unroll
    for (int o = 16; o > 0; o >>= 1) part += __shfl_xor_sync(0xffffffffu, part, o);
    __shared__ float ws[8];
    if ((threadIdx.x & 31) == 0) ws[threadIdx.x >> 5] = part;
    __syncthreads();
    if (threadIdx.x == 0) {
        float bs = 0.f;
        for (int w = 0; w < (int)(blockDim.x >> 5); w++) bs += ws[w];
        atomicAdd(&g_acc, (double)bs);
    }
}

// ---------------------------------------------------------------------------
__global__ void vq_finalize_kernel(float* __restrict__ out) {
    out[(size_t)N_POINTS * DIM] = (float)(1.25 * g_acc / (double)(N_POINTS * DIM));
}

// ---------------------------------------------------------------------------
extern "C" void kernel_launch(void* const* d_in, const int* in_sizes, int n_in,
                              void* d_out, int out_size) {
    const float* x  = (const float*)d_in[0];
    const float* cb = (const float*)d_in[1];
    float* out = (float*)d_out;
    (void)in_sizes; (void)n_in; (void)out_size;

    cudaFuncSetAttribute(vq_mma_kernel, cudaFuncAttributeMaxDynamicSharedMemorySize,
                         SMEM_DYN);

    vq_reset_kernel<<<1, 1>>>();
    vq_csq_kernel<<<K_CODES, 64>>>(cb);
    vq_cbhalf_kernel<<<1024, 256>>>(cb);
    vq_mma_kernel<<<N_POINTS / BM, THREADS, SMEM_DYN>>>(x);
    vq_cleanup_kernel<<<1024, 256>>>(x, cb);
    vq_gather_kernel<<<4096, 256>>>(x, cb, out);
    vq_finalize_kernel<<<1, 1>>>(out);
}

// round 7
// speedup vs baseline: 4.1529x; 1.4637x over previous
#include <cuda_runtime.h>
#include <cuda_fp16.h>
#include <cfloat>
#include <cstdint>

#define N_POINTS 32768
#define DIM      256
#define D4       (DIM / 4)
#define K_CODES  4096
#define BM       128
#define BN       128
#define NTILE    (K_CODES / BN)       // 32
#define THREADS  256
#define MARGIN   6e-3f
#define CLB      8                    // flagged points per cleanup block

// smem layout (bytes from dynamic base)
#define SM_CSQ  0                      // 4096 f32 = 16 KB
#define SM_A    16384                  // 128 rows x 512 B (fp16) = 64 KB
#define SM_B    81920                  // 2 x 16 KB chunk buffers
#define SMEM_DYN 114688                // 112 KB -> 2 CTAs/SM

typedef unsigned int uint32;

// ---------------------------------------------------------------------------
// Device scratch (static — no allocations allowed)
__device__ float  g_csq[K_CODES];
__device__ int    g_idx[N_POINTS];
__device__ double g_acc;
__device__ int    g_nflag;
__device__ int    g_flag[N_POINTS];
__device__ __align__(128) __half g_cbh[K_CODES * DIM];

// ---------------------------------------------------------------------------
__device__ __forceinline__ uint32 smem_u32(const void* p) {
    return (uint32)__cvta_generic_to_shared(p);
}
__device__ __forceinline__ void cp_async16(uint32 dst, const void* src) {
    asm volatile("cp.async.cg.shared.global [%0], [%1], 16;" :: "r"(dst), "l"(src));
}
#define CP_COMMIT()  asm volatile("cp.async.commit_group;" ::: "memory")
#define CP_WAIT(n)   asm volatile("cp.async.wait_group %0;" :: "n"(n) : "memory")

__device__ __forceinline__ void ldsm4(uint32* r, uint32 addr) {
    asm volatile("ldmatrix.sync.aligned.m8n8.x4.shared.b16 {%0,%1,%2,%3}, [%4];"
                 : "=r"(r[0]), "=r"(r[1]), "=r"(r[2]), "=r"(r[3]) : "r"(addr));
}
__device__ __forceinline__ void mma16816(float* d, const uint32* a, const uint32* b) {
    asm volatile("mma.sync.aligned.m16n8k16.row.col.f32.f16.f16.f32 "
                 "{%0,%1,%2,%3}, {%4,%5,%6,%7}, {%8,%9}, {%0,%1,%2,%3};"
                 : "+f"(d[0]), "+f"(d[1]), "+f"(d[2]), "+f"(d[3])
                 : "r"(a[0]), "r"(a[1]), "r"(a[2]), "r"(a[3]), "r"(b[0]), "r"(b[1]));
}

// ---------------------------------------------------------------------------
__global__ void vq_reset_kernel() { g_acc = 0.0; g_nflag = 0; }

// ---------------------------------------------------------------------------
__global__ void vq_csq_kernel(const float* __restrict__ cb) {
    int row = blockIdx.x;
    float4 v = reinterpret_cast<const float4*>(cb + (size_t)row * DIM)[threadIdx.x];
    float s = v.x * v.x + v.y * v.y + v.z * v.z + v.w * v.w;
    #pragma unroll
    for (int o = 16; o > 0; o >>= 1) s += __shfl_xor_sync(0xffffffffu, s, o);
    __shared__ float ws[2];
    if ((threadIdx.x & 31) == 0) ws[threadIdx.x >> 5] = s;
    __syncthreads();
    if (threadIdx.x == 0) g_csq[row] = ws[0] + ws[1];
}

// ---------------------------------------------------------------------------
__global__ void vq_cbhalf_kernel(const float* __restrict__ cb) {
    for (int e = blockIdx.x * blockDim.x + threadIdx.x; e < K_CODES * DIM;
         e += gridDim.x * blockDim.x)
        g_cbh[e] = __float2half_rn(cb[e]);
}

// ---------------------------------------------------------------------------
// Stream one B chunk: 128 codes x 64 dims fp16 = 16 KB, swizzled rows of 128 B.
__device__ __forceinline__ void load_chunk(uint32 smB, int it, int tid) {
    const int tile = it >> 2, kc = it & 3, buf = it & 1;
    const uint32 dst = smB + buf * 16384;
    const __half* src = g_cbh + (size_t)tile * BN * DIM + kc * 64;
    #pragma unroll
    for (int r = 0; r < 4; r++) {
        int idx  = tid + r * THREADS;        // 0..1023
        int code = idx >> 3, seg = idx & 7;
        uint32 off = code * 128 + ((seg * 16) ^ ((code & 7) << 4));
        cp_async16(dst + off, src + (size_t)code * DIM + seg * 8);
    }
}

// ---------------------------------------------------------------------------
// 1-pass fp16 tensor-core argmin, warp tile m32 x n64, 2 CTAs/SM.
__global__ __launch_bounds__(THREADS, 2)
void vq_mma_kernel(const float* __restrict__ x) {
    extern __shared__ unsigned char smb[];
    const uint32 sbase = smem_u32(smb);
    float* sCsq = reinterpret_cast<float*>(smb + SM_CSQ);

    const int tid  = threadIdx.x;
    const int lane = tid & 31;
    const int warp = tid >> 5;
    const int wm   = warp >> 1;          // 0..3 -> rows wm*32..+31
    const int wn   = warp & 1;           // 0..1 -> codes wn*64..+63 in tile
    const int pbase = blockIdx.x * BM;

    load_chunk(sbase + SM_B, 0, tid);
    CP_COMMIT();

    for (int i = tid; i < K_CODES; i += THREADS) sCsq[i] = g_csq[i];

    // A tile: 128 pts x 256 dims -> fp16, swizzled rows of 512 B
    {
        const float4* xg = reinterpret_cast<const float4*>(x + (size_t)pbase * DIM);
        #pragma unroll
        for (int i = 0; i < 16; i++) {
            int idx = tid + i * THREADS;     // (row, seg16B): 128*32
            int row = idx >> 5, seg = idx & 31;
            float4 v0 = xg[row * 64 + seg * 2];
            float4 v1 = xg[row * 64 + seg * 2 + 1];
            __half h[8];
            h[0] = __float2half_rn(v0.x); h[1] = __float2half_rn(v0.y);
            h[2] = __float2half_rn(v0.z); h[3] = __float2half_rn(v0.w);
            h[4] = __float2half_rn(v1.x); h[5] = __float2half_rn(v1.y);
            h[6] = __float2half_rn(v1.z); h[7] = __float2half_rn(v1.w);
            uint32 off = row * 512 + ((seg * 16) ^ ((row & 7) << 4));
            *reinterpret_cast<uint4*>(smb + SM_A + off) = *reinterpret_cast<uint4*>(h);
        }
    }

    // Fragment addressing
    const uint32 a_row  = wm * 32 + (lane & 7) + ((lane >> 3) & 1) * 8;
    const uint32 a_k16  = ((lane >> 4) & 1) * 16;
    const uint32 swz    = (lane & 7) << 4;
    const uint32 aBase0 = sbase + SM_A + a_row * 512;          // mi=0
    const uint32 aBase1 = aBase0 + 16 * 512;                    // mi=1
    const uint32 b_cloc = ((lane >> 4) & 1) * 8 + (lane & 7);
    const uint32 b_k16  = ((lane >> 3) & 1) * 16;

    float dacc[2][8][4];
    #pragma unroll
    for (int mi = 0; mi < 2; mi++)
        #pragma unroll
        for (int nf = 0; nf < 8; nf++)
            #pragma unroll
            for (int q = 0; q < 4; q++) dacc[mi][nf][q] = 0.f;

    // Per-thread argmin state: 4 row-slots (mi,q)
    float best[4] = {FLT_MAX, FLT_MAX, FLT_MAX, FLT_MAX};
    float sec [4] = {FLT_MAX, FLT_MAX, FLT_MAX, FLT_MAX};
    int   bidx[4] = {0, 0, 0, 0};

    __syncthreads();

    for (int it = 0; it < NTILE * 4; it++) {
        const int tile = it >> 2, kc = it & 3, buf = it & 1;
        __syncthreads();                       // prior reads of buf^1 done
        if (it + 1 < NTILE * 4) load_chunk(sbase + SM_B, it + 1, tid);
        CP_COMMIT();
        CP_WAIT(1);                            // chunk `it` resident
        __syncthreads();

        const uint32 bBase = sbase + SM_B + buf * 16384;

        #pragma unroll
        for (int ks = 0; ks < 4; ks++) {
            uint32 a0[4], a1[4];
            uint32 aoff = ((uint32)(kc * 128 + ks * 32) + a_k16) ^ swz;
            ldsm4(a0, aBase0 + aoff);
            ldsm4(a1, aBase1 + aoff);
            uint32 boff = ((uint32)(ks * 32) + b_k16) ^ swz;
            #pragma unroll
            for (int np = 0; np < 4; np++) {
                uint32 bh[4];
                ldsm4(bh, bBase + (uint32)(wn * 64 + np * 16 + b_cloc) * 128 + boff);
                mma16816(dacc[0][2 * np],     a0, bh);
                mma16816(dacc[1][2 * np],     a1, bh);
                mma16816(dacc[0][2 * np + 1], a0, bh + 2);
                mma16816(dacc[1][2 * np + 1], a1, bh + 2);
            }
        }

        if (kc == 3) {
            const int cb0 = tile * BN + wn * 64 + (lane & 3) * 2;
            #pragma unroll
            for (int nf = 0; nf < 8; nf++) {
                const int ci0 = cb0 + nf * 8;
                const float cs0 = sCsq[ci0], cs1 = sCsq[ci0 + 1];
                #pragma unroll
                for (int mi = 0; mi < 2; mi++)
                    #pragma unroll
                    for (int q = 0; q < 2; q++) {
                        const int k = mi * 2 + q;
                        float s0 = fmaf(-2.f, dacc[mi][nf][2 * q],     cs0);
                        float s1 = fmaf(-2.f, dacc[mi][nf][2 * q + 1], cs1);
                        if (s0 < best[k]) { sec[k] = best[k]; best[k] = s0; bidx[k] = ci0; }
                        else if (s0 < sec[k]) sec[k] = s0;
                        if (s1 < best[k]) { sec[k] = best[k]; best[k] = s1; bidx[k] = ci0 + 1; }
                        else if (s1 < sec[k]) sec[k] = s1;
                        dacc[mi][nf][2 * q] = 0.f; dacc[mi][nf][2 * q + 1] = 0.f;
                    }
            }
        }
    }

    // Quad-lane merge (lanes differing in lane&3 hold different codes, same rows)
    float mb[4], ms[4];
    int   mi_[4];
    #pragma unroll
    for (int k = 0; k < 4; k++) {
        float b = best[k], s = sec[k];
        int   i = bidx[k];
        #pragma unroll
        for (int off = 1; off <= 2; off <<= 1) {
            float ob = __shfl_xor_sync(0xffffffffu, b, off);
            float os = __shfl_xor_sync(0xffffffffu, s, off);
            int   oi = __shfl_xor_sync(0xffffffffu, i, off);
            if (ob < b)      { s = fminf(b, os); b = ob; i = oi; }
            else if (b < ob) { s = fminf(s, ob); }
            else             { s = b; i = min(i, oi); }
        }
        mb[k] = b; ms[k] = s; mi_[k] = i;
    }

    // Cross-warp-column merge via smem (reuse B region)
    float* mB = reinterpret_cast<float*>(smb + SM_B);     // [2][128]
    float* mS = mB + 256;
    int*   mI = reinterpret_cast<int*>(mS + 256);
    __syncthreads();
    if ((lane & 3) == 0) {
        #pragma unroll
        for (int k = 0; k < 4; k++) {
            int row = wm * 32 + (k >> 1) * 16 + (lane >> 2) + (k & 1) * 8;
            int s2  = wn * 128 + row;
            mB[s2] = mb[k]; mS[s2] = ms[k]; mI[s2] = mi_[k];
        }
    }
    __syncthreads();
    if (tid < BM) {
        float b0 = mB[tid], s0 = mS[tid], b1 = mB[128 + tid], s1 = mS[128 + tid];
        int   i0 = mI[tid], i1 = mI[128 + tid];
        float b, s; int i;
        if (b0 < b1)      { b = b0; i = i0; s = fminf(s0, b1); }
        else if (b1 < b0) { b = b1; i = i1; s = fminf(s1, b0); }
        else              { b = b0; i = min(i0, i1); s = b0; }
        const int pg = pbase + tid;
        if (s - b <= MARGIN) {
            int pos = atomicAdd(&g_nflag, 1);
            g_flag[pos] = pg;
        } else {
            g_idx[pg] = i;
        }
    }
}

// ---------------------------------------------------------------------------
// Exact fp32 resolution for flagged points — 8 points per block share one
// codebook sweep through smem tiles of 32 codes. Warp = point, lane = code
// (code ≡ lane mod 32, ascending per lane; cross-lane lexicographic merge).
__global__ __launch_bounds__(256, 2)
void vq_cleanup_kernel(const float* __restrict__ x, const float* __restrict__ cb) {
    __shared__ float sx[CLB][DIM];         // 8 KB
    __shared__ float sc[32][DIM + 4];      // 32 x 260 floats, conflict-free rows
    const int tid  = threadIdx.x;
    const int lane = tid & 31;
    const int w    = tid >> 5;
    const int nf   = g_nflag;

    for (int g = blockIdx.x * CLB; g < nf; g += gridDim.x * CLB) {
        const int npts = min(CLB, nf - g);
        __syncthreads();                   // protect sx reuse across groups
        for (int i = tid; i < npts * D4; i += 256) {
            int pt = i >> 6, c4 = i & 63;
            int p = g_flag[g + pt];
            *reinterpret_cast<float4*>(&sx[pt][c4 * 4]) =
                reinterpret_cast<const float4*>(x)[(size_t)p * D4 + c4];
        }

        float best = FLT_MAX;
        int   bi   = 0x7fffffff;

        for (int t = 0; t < K_CODES / 32; t++) {
            __syncthreads();               // readers of sc done
            for (int i = tid; i < 32 * D4; i += 256) {
                int cr = i >> 6, c4 = i & 63;
                *reinterpret_cast<float4*>(&sc[cr][c4 * 4]) =
                    reinterpret_cast<const float4*>(cb)[(size_t)(t * 32 + cr) * D4 + c4];
            }
            __syncthreads();
            if (w < npts) {
                float dot = 0.f;
                #pragma unroll 16
                for (int k = 0; k < D4; k++) {
                    float4 cv = *reinterpret_cast<const float4*>(&sc[lane][k * 4]);
                    float4 xv = *reinterpret_cast<const float4*>(&sx[w][k * 4]);
                    dot = fmaf(xv.x, cv.x, dot); dot = fmaf(xv.y, cv.y, dot);
                    dot = fmaf(xv.z, cv.z, dot); dot = fmaf(xv.w, cv.w, dot);
                }
                const int ci = t * 32 + lane;
                float s = fmaf(-2.f, dot, __ldg(&g_csq[ci]));
                if (s < best) { best = s; bi = ci; }   // ascending per lane
            }
        }

        // Cross-lane lexicographic (score, idx) min
        #pragma unroll
        for (int off = 16; off > 0; off >>= 1) {
            float ob = __shfl_xor_sync(0xffffffffu, best, off);
            int   oi = __shfl_xor_sync(0xffffffffu, bi, off);
            if (ob < best || (ob == best && oi < bi)) { best = ob; bi = oi; }
        }
        if (lane == 0 && w < npts) g_idx[g_flag[g + w]] = bi;
    }
}

// ---------------------------------------------------------------------------
__global__ void vq_gather_kernel(const float* __restrict__ x,
                                 const float* __restrict__ cb,
                                 float* __restrict__ out) {
    const int total4 = N_POINTS * D4;
    float part = 0.f;
    for (int i4 = blockIdx.x * blockDim.x + threadIdx.x; i4 < total4;
         i4 += gridDim.x * blockDim.x) {
        int p  = i4 >> 6;
        int c4 = i4 & 63;
        int ci = g_idx[p];
        float4 xv = reinterpret_cast<const float4*>(x)[i4];
        float4 qv = reinterpret_cast<const float4*>(cb)[(size_t)ci * D4 + c4];
        float4 d, o;
        d.x = qv.x - xv.x; d.y = qv.y - xv.y; d.z = qv.z - xv.z; d.w = qv.w - xv.w;
        o.x = xv.x + d.x;  o.y = xv.y + d.y;  o.z = xv.z + d.z;  o.w = xv.w + d.w;
        reinterpret_cast<float4*>(out)[i4] = o;
        part += d.x * d.x + d.y * d.y + d.z * d.z + d.w * d.w;
    }
    #pragma unroll
    for (int o = 16; o > 0; o >>= 1) part += __shfl_xor_sync(0xffffffffu, part, o);
    __shared__ float ws[8];
    if ((threadIdx.x & 31) == 0) ws[threadIdx.x >> 5] = part;
    __syncthreads();
    if (threadIdx.x == 0) {
        float bs = 0.f;
        for (int w = 0; w < (int)(blockDim.x >> 5); w++) bs += ws[w];
        atomicAdd(&g_acc, (double)bs);
    }
}

// ---------------------------------------------------------------------------
__global__ void vq_finalize_kernel(float* __restrict__ out) {
    out[(size_t)N_POINTS * DIM] = (float)(1.25 * g_acc / (double)(N_POINTS * DIM));
}

// ---------------------------------------------------------------------------
extern "C" void kernel_launch(void* const* d_in, const int* in_sizes, int n_in,
                              void* d_out, int out_size) {
    const float* x  = (const float*)d_in[0];
    const float* cb = (const float*)d_in[1];
    float* out = (float*)d_out;
    (void)in_sizes; (void)n_in; (void)out_size;

    cudaFuncSetAttribute(vq_mma_kernel, cudaFuncAttributeMaxDynamicSharedMemorySize,
                         SMEM_DYN);

    vq_reset_kernel<<<1, 1>>>();
    vq_csq_kernel<<<K_CODES, 64>>>(cb);
    vq_cbhalf_kernel<<<1024, 256>>>(cb);
    vq_mma_kernel<<<N_POINTS / BM, THREADS, SMEM_DYN>>>(x);
    vq_cleanup_kernel<<<64, 256>>>(x, cb);
    vq_gather_kernel<<<4096, 256>>>(x, cb, out);
    vq_finalize_kernel<<<1, 1>>>(out);
}

// round 9
// speedup vs baseline: 4.3983x; 1.0591x over previous
#include <cuda_runtime.h>
#include <cuda_fp16.h>
#include <cfloat>
#include <cstdint>

#define N_POINTS 32768
#define DIM      256
#define D4       (DIM / 4)
#define K_CODES  4096
#define BM       128
#define BN       128
#define NTILE    (K_CODES / BN)       // 32
#define NCHUNK   (NTILE * 4)          // 128 chunks of 64 dims
#define THREADS  256
#define MARGIN   6e-3f
#define CLB      8                    // flagged points per cleanup block
#define CLGRID   128                  // cleanup blocks (capacity 1024 points)

// smem byte offsets, mma kernel
#define SM_A    0                      // 128 rows x 512 B (fp16) = 64 KB
#define SM_B    65536                  // 3 x 16 KB chunk buffers = 48 KB
#define SMEM_DYN 114688                // 112 KB -> 2 CTAs/SM

// cleanup smem: sx 8*256*4 = 8 KB, sc 64 rows x 260 floats = 66560 B
#define CL_SC_OFF   (CLB * DIM)
#define CL_SMEM     ((CLB * DIM + 64 * 260) * 4)   // 74752 B

typedef unsigned int uint32;

// ---------------------------------------------------------------------------
// Device scratch (static — no allocations allowed)
__device__ float  g_csq[K_CODES];
__device__ int    g_idx[N_POINTS];
__device__ double g_acc;
__device__ int    g_nflag;
__device__ int    g_flag[N_POINTS];
__device__ __align__(128) __half g_cbh[K_CODES * DIM];

// ---------------------------------------------------------------------------
__device__ __forceinline__ uint32 smem_u32(const void* p) {
    return (uint32)__cvta_generic_to_shared(p);
}
__device__ __forceinline__ void cp_async16(uint32 dst, const void* src) {
    asm volatile("cp.async.cg.shared.global [%0], [%1], 16;" :: "r"(dst), "l"(src));
}
#define CP_COMMIT()  asm volatile("cp.async.commit_group;" ::: "memory")
#define CP_WAIT(n)   asm volatile("cp.async.wait_group %0;" :: "n"(n) : "memory")

__device__ __forceinline__ void ldsm4(uint32* r, uint32 addr) {
    asm volatile("ldmatrix.sync.aligned.m8n8.x4.shared.b16 {%0,%1,%2,%3}, [%4];"
                 : "=r"(r[0]), "=r"(r[1]), "=r"(r[2]), "=r"(r[3]) : "r"(addr));
}
__device__ __forceinline__ void mma16816(float* d, const uint32* a, const uint32* b) {
    asm volatile("mma.sync.aligned.m16n8k16.row.col.f32.f16.f16.f32 "
                 "{%0,%1,%2,%3}, {%4,%5,%6,%7}, {%8,%9}, {%0,%1,%2,%3};"
                 : "+f"(d[0]), "+f"(d[1]), "+f"(d[2]), "+f"(d[3])
                 : "r"(a[0]), "r"(a[1]), "r"(a[2]), "r"(a[3]), "r"(b[0]), "r"(b[1]));
}

// ---------------------------------------------------------------------------
__global__ void vq_reset_kernel() { g_acc = 0.0; g_nflag = 0; }

// ---------------------------------------------------------------------------
__global__ void vq_csq_kernel(const float* __restrict__ cb) {
    int row = blockIdx.x;
    float4 v = reinterpret_cast<const float4*>(cb + (size_t)row * DIM)[threadIdx.x];
    float s = v.x * v.x + v.y * v.y + v.z * v.z + v.w * v.w;
    #pragma unroll
    for (int o = 16; o > 0; o >>= 1) s += __shfl_xor_sync(0xffffffffu, s, o);
    __shared__ float ws[2];
    if ((threadIdx.x & 31) == 0) ws[threadIdx.x >> 5] = s;
    __syncthreads();
    if (threadIdx.x == 0) g_csq[row] = ws[0] + ws[1];
}

// ---------------------------------------------------------------------------
__global__ void vq_cbhalf_kernel(const float* __restrict__ cb) {
    for (int e = blockIdx.x * blockDim.x + threadIdx.x; e < K_CODES * DIM;
         e += gridDim.x * blockDim.x)
        g_cbh[e] = __float2half_rn(cb[e]);
}

// ---------------------------------------------------------------------------
// Stream one B chunk: 128 codes x 64 dims fp16 = 16 KB, swizzled rows of 128 B.
__device__ __forceinline__ void load_chunk(uint32 smB, int it, int tid) {
    const int tile = it >> 2, kc = it & 3;
    const uint32 dst = smB + (uint32)(it % 3) * 16384;
    const __half* src = g_cbh + (size_t)tile * BN * DIM + kc * 64;
    #pragma unroll
    for (int r = 0; r < 4; r++) {
        int idx  = tid + r * THREADS;        // 0..1023
        int code = idx >> 3, seg = idx & 7;
        uint32 off = code * 128 + ((seg * 16) ^ ((code & 7) << 4));
        cp_async16(dst + off, src + (size_t)code * DIM + seg * 8);
    }
}

// ---------------------------------------------------------------------------
// 1-pass fp16 tensor-core argmin, warp tile m32 x n64, 2 CTAs/SM.
// (unchanged from round 8 — semantics identical to the round-7 passing kernel)
__global__ __launch_bounds__(THREADS, 2)
void vq_mma_kernel(const float* __restrict__ x) {
    extern __shared__ unsigned char smb[];
    const uint32 sbase = smem_u32(smb);

    const int tid  = threadIdx.x;
    const int lane = tid & 31;
    const int warp = tid >> 5;
    const int wm   = warp >> 1;
    const int wn   = warp & 1;
    const int pbase = blockIdx.x * BM;

    load_chunk(sbase + SM_B, 0, tid); CP_COMMIT();
    load_chunk(sbase + SM_B, 1, tid); CP_COMMIT();

    {
        const float4* xg = reinterpret_cast<const float4*>(x + (size_t)pbase * DIM);
        #pragma unroll
        for (int i = 0; i < 16; i++) {
            int idx = tid + i * THREADS;
            int row = idx >> 5, seg = idx & 31;
            float4 v0 = xg[row * 64 + seg * 2];
            float4 v1 = xg[row * 64 + seg * 2 + 1];
            __half h[8];
            h[0] = __float2half_rn(v0.x); h[1] = __float2half_rn(v0.y);
            h[2] = __float2half_rn(v0.z); h[3] = __float2half_rn(v0.w);
            h[4] = __float2half_rn(v1.x); h[5] = __float2half_rn(v1.y);
            h[6] = __float2half_rn(v1.z); h[7] = __float2half_rn(v1.w);
            uint32 off = row * 512 + ((seg * 16) ^ ((row & 7) << 4));
            *reinterpret_cast<uint4*>(smb + SM_A + off) = *reinterpret_cast<uint4*>(h);
        }
    }

    const uint32 a_row  = wm * 32 + (lane & 7) + ((lane >> 3) & 1) * 8;
    const uint32 a_k16  = ((lane >> 4) & 1) * 16;
    const uint32 swz    = (lane & 7) << 4;
    const uint32 aBase0 = sbase + SM_A + a_row * 512;
    const uint32 aBase1 = aBase0 + 16 * 512;
    const uint32 b_cloc = ((lane >> 4) & 1) * 8 + (lane & 7);
    const uint32 b_k16  = ((lane >> 3) & 1) * 16;

    float dacc[2][8][4];
    #pragma unroll
    for (int mi = 0; mi < 2; mi++)
        #pragma unroll
        for (int nf = 0; nf < 8; nf++)
            #pragma unroll
            for (int q = 0; q < 4; q++) dacc[mi][nf][q] = 0.f;

    float best[4] = {FLT_MAX, FLT_MAX, FLT_MAX, FLT_MAX};
    float sec [4] = {FLT_MAX, FLT_MAX, FLT_MAX, FLT_MAX};
    int   bidx[4] = {0, 0, 0, 0};

    for (int it = 0; it < NCHUNK; it++) {
        const int tile = it >> 2, kc = it & 3;

        CP_WAIT(1);
        __syncthreads();

        if (it + 2 < NCHUNK) load_chunk(sbase + SM_B, it + 2, tid);
        CP_COMMIT();

        const uint32 bBase = sbase + SM_B + (uint32)(it % 3) * 16384;

        #pragma unroll
        for (int ks = 0; ks < 4; ks++) {
            uint32 a0[4], a1[4];
            uint32 aoff = ((uint32)(kc * 128 + ks * 32) + a_k16) ^ swz;
            ldsm4(a0, aBase0 + aoff);
            ldsm4(a1, aBase1 + aoff);
            uint32 boff = ((uint32)(ks * 32) + b_k16) ^ swz;
            #pragma unroll
            for (int np = 0; np < 4; np++) {
                uint32 bh[4];
                ldsm4(bh, bBase + (uint32)(wn * 64 + np * 16 + b_cloc) * 128 + boff);
                mma16816(dacc[0][2 * np],     a0, bh);
                mma16816(dacc[1][2 * np],     a1, bh);
                mma16816(dacc[0][2 * np + 1], a0, bh + 2);
                mma16816(dacc[1][2 * np + 1], a1, bh + 2);
            }
        }

        if (kc == 3) {
            const int cb0 = tile * BN + wn * 64 + (lane & 3) * 2;
            #pragma unroll
            for (int mi = 0; mi < 2; mi++)
                #pragma unroll
                for (int q = 0; q < 2; q++) {
                    const int k = mi * 2 + q;
                    float s[16];
                    float tmin = FLT_MAX;
                    #pragma unroll
                    for (int nf = 0; nf < 8; nf++) {
                        const int ci0 = cb0 + nf * 8;
                        float s0 = fmaf(-2.f, dacc[mi][nf][2 * q],     __ldg(&g_csq[ci0]));
                        float s1 = fmaf(-2.f, dacc[mi][nf][2 * q + 1], __ldg(&g_csq[ci0 + 1]));
                        s[2 * nf] = s0; s[2 * nf + 1] = s1;
                        tmin = fminf(tmin, fminf(s0, s1));
                        dacc[mi][nf][2 * q] = 0.f; dacc[mi][nf][2 * q + 1] = 0.f;
                    }
                    if (tmin <= sec[k]) {
                        #pragma unroll
                        for (int e = 0; e < 16; e++) {
                            float sv = s[e];
                            int   ci = cb0 + (e >> 1) * 8 + (e & 1);
                            if (sv < best[k]) { sec[k] = best[k]; best[k] = sv; bidx[k] = ci; }
                            else if (sv < sec[k]) sec[k] = sv;
                        }
                    }
                }
        }
    }

    float mb[4], ms[4];
    int   mi_[4];
    #pragma unroll
    for (int k = 0; k < 4; k++) {
        float b = best[k], s = sec[k];
        int   i = bidx[k];
        #pragma unroll
        for (int off = 1; off <= 2; off <<= 1) {
            float ob = __shfl_xor_sync(0xffffffffu, b, off);
            float os = __shfl_xor_sync(0xffffffffu, s, off);
            int   oi = __shfl_xor_sync(0xffffffffu, i, off);
            if (ob < b)      { s = fminf(b, os); b = ob; i = oi; }
            else if (b < ob) { s = fminf(s, ob); }
            else             { s = b; i = min(i, oi); }
        }
        mb[k] = b; ms[k] = s; mi_[k] = i;
    }

    float* mB = reinterpret_cast<float*>(smb + SM_B);
    float* mS = mB + 256;
    int*   mI = reinterpret_cast<int*>(mS + 256);
    __syncthreads();
    if ((lane & 3) == 0) {
        #pragma unroll
        for (int k = 0; k < 4; k++) {
            int row = wm * 32 + (k >> 1) * 16 + (lane >> 2) + (k & 1) * 8;
            int s2  = wn * 128 + row;
            mB[s2] = mb[k]; mS[s2] = ms[k]; mI[s2] = mi_[k];
        }
    }
    __syncthreads();
    if (tid < BM) {
        float b0 = mB[tid], s0 = mS[tid], b1 = mB[128 + tid], s1 = mS[128 + tid];
        int   i0 = mI[tid], i1 = mI[128 + tid];
        float b, s; int i;
        if (b0 < b1)      { b = b0; i = i0; s = fminf(s0, b1); }
        else if (b1 < b0) { b = b1; i = i1; s = fminf(s1, b0); }
        else              { b = b0; i = min(i0, i1); s = b0; }
        const int pg = pbase + tid;
        if (s - b <= MARGIN) {
            int pos = atomicAdd(&g_nflag, 1);
            g_flag[pos] = pg;
        } else {
            g_idx[pg] = i;
        }
    }
}

// ---------------------------------------------------------------------------
// Exact fp32 resolution for flagged points. 8 points/block, 64-code smem tiles.
// Each lane owns TWO codes (lane, lane+32) as two INDEPENDENT sequential fmaf
// chains — each chain keeps the exact x.x,x.y,x.z,x.w dim order used by all
// passing rounds (the exact-path summation order is load-bearing: round 8
// proved a reorder flips near-tie points).
__global__ __launch_bounds__(256, 1)
void vq_cleanup_kernel(const float* __restrict__ x, const float* __restrict__ cb) {
    extern __shared__ float clsm[];
    float* sx = clsm;                    // [CLB][DIM]
    float* sc = clsm + CL_SC_OFF;        // [64][260]
    const int tid  = threadIdx.x;
    const int lane = tid & 31;
    const int w    = tid >> 5;
    const int nf   = g_nflag;

    for (int g = blockIdx.x * CLB; g < nf; g += gridDim.x * CLB) {
        const int npts = min(CLB, nf - g);
        __syncthreads();                   // protect sx reuse across groups
        for (int i = tid; i < npts * D4; i += 256) {
            int pt = i >> 6, c4 = i & 63;
            int p = g_flag[g + pt];
            *reinterpret_cast<float4*>(&sx[pt * DIM + c4 * 4]) =
                reinterpret_cast<const float4*>(x)[(size_t)p * D4 + c4];
        }

        float best = FLT_MAX;
        int   bi   = 0x7fffffff;

        for (int t = 0; t < K_CODES / 64; t++) {
            __syncthreads();               // readers of sc done
            for (int i = tid; i < 64 * D4; i += 256) {
                int cr = i >> 6, c4 = i & 63;
                *reinterpret_cast<float4*>(&sc[cr * 260 + c4 * 4]) =
                    reinterpret_cast<const float4*>(cb)[(size_t)(t * 64 + cr) * D4 + c4];
            }
            __syncthreads();
            if (w < npts) {
                const float* xr = &sx[w * DIM];
                const float* cA = &sc[lane * 260];
                const float* cB = &sc[(lane + 32) * 260];
                float dA = 0.f, dB = 0.f;
                #pragma unroll 16
                for (int k = 0; k < D4; k++) {
                    float4 xv = *reinterpret_cast<const float4*>(&xr[k * 4]);
                    float4 av = *reinterpret_cast<const float4*>(&cA[k * 4]);
                    float4 bv = *reinterpret_cast<const float4*>(&cB[k * 4]);
                    dA = fmaf(xv.x, av.x, dA); dA = fmaf(xv.y, av.y, dA);
                    dA = fmaf(xv.z, av.z, dA); dA = fmaf(xv.w, av.w, dA);
                    dB = fmaf(xv.x, bv.x, dB); dB = fmaf(xv.y, bv.y, dB);
                    dB = fmaf(xv.z, bv.z, dB); dB = fmaf(xv.w, bv.w, dB);
                }
                const int ciA = t * 64 + lane;
                const int ciB = ciA + 32;
                float sA = fmaf(-2.f, dA, __ldg(&g_csq[ciA]));
                float sB = fmaf(-2.f, dB, __ldg(&g_csq[ciB]));
                // A before B: indices ascending within lane; strict < = first min
                if (sA < best) { best = sA; bi = ciA; }
                if (sB < best) { best = sB; bi = ciB; }
            }
        }

        // Cross-lane lexicographic (score, idx) min
        #pragma unroll
        for (int off = 16; off > 0; off >>= 1) {
            float ob = __shfl_xor_sync(0xffffffffu, best, off);
            int   oi = __shfl_xor_sync(0xffffffffu, bi, off);
            if (ob < best || (ob == best && oi < bi)) { best = ob; bi = oi; }
        }
        if (lane == 0 && w < npts) g_idx[g_flag[g + w]] = bi;
    }
}

// ---------------------------------------------------------------------------
__global__ void vq_gather_kernel(const float* __restrict__ x,
                                 const float* __restrict__ cb,
                                 float* __restrict__ out) {
    const int total4 = N_POINTS * D4;
    float part = 0.f;
    for (int i4 = blockIdx.x * blockDim.x + threadIdx.x; i4 < total4;
         i4 += gridDim.x * blockDim.x) {
        int p  = i4 >> 6;
        int c4 = i4 & 63;
        int ci = g_idx[p];
        float4 xv = reinterpret_cast<const float4*>(x)[i4];
        float4 qv = reinterpret_cast<const float4*>(cb)[(size_t)ci * D4 + c4];
        float4 d, o;
        d.x = qv.x - xv.x; d.y = qv.y - xv.y; d.z = qv.z - xv.z; d.w = qv.w - xv.w;
        o.x = xv.x + d.x;  o.y = xv.y + d.y;  o.z = xv.z + d.z;  o.w = xv.w + d.w;
        reinterpret_cast<float4*>(out)[i4] = o;
        part += d.x * d.x + d.y * d.y + d.z * d.z + d.w * d.w;
    }
    #pragma unroll
    for (int o = 16; o > 0; o >>= 1) part += __shfl_xor_sync(0xffffffffu, part, o);
    __shared__ float ws[8];
    if ((threadIdx.x & 31) == 0) ws[threadIdx.x >> 5] = part;
    __syncthreads();
    if (threadIdx.x == 0) {
        float bs = 0.f;
        for (int w = 0; w < (int)(blockDim.x >> 5); w++) bs += ws[w];
        atomicAdd(&g_acc, (double)bs);
    }
}

// ---------------------------------------------------------------------------
__global__ void vq_finalize_kernel(float* __restrict__ out) {
    out[(size_t)N_POINTS * DIM] = (float)(1.25 * g_acc / (double)(N_POINTS * DIM));
}

// ---------------------------------------------------------------------------
extern "C" void kernel_launch(void* const* d_in, const int* in_sizes, int n_in,
                              void* d_out, int out_size) {
    const float* x  = (const float*)d_in[0];
    const float* cb = (const float*)d_in[1];
    float* out = (float*)d_out;
    (void)in_sizes; (void)n_in; (void)out_size;

    cudaFuncSetAttribute(vq_mma_kernel, cudaFuncAttributeMaxDynamicSharedMemorySize,
                         SMEM_DYN);
    cudaFuncSetAttribute(vq_cleanup_kernel, cudaFuncAttributeMaxDynamicSharedMemorySize,
                         CL_SMEM);

    vq_reset_kernel<<<1, 1>>>();
    vq_csq_kernel<<<K_CODES, 64>>>(cb);
    vq_cbhalf_kernel<<<1024, 256>>>(cb);
    vq_mma_kernel<<<N_POINTS / BM, THREADS, SMEM_DYN>>>(x);
    vq_cleanup_kernel<<<CLGRID, 256, CL_SMEM>>>(x, cb);
    vq_gather_kernel<<<4096, 256>>>(x, cb, out);
    vq_finalize_kernel<<<1, 1>>>(out);
}

// round 10
// speedup vs baseline: 4.7337x; 1.0763x over previous
#include <cuda_runtime.h>
#include <cuda_fp16.h>
#include <cfloat>
#include <cstdint>

#define N_POINTS 32768
#define DIM      256
#define D4       (DIM / 4)
#define K_CODES  4096
#define BM       128
#define BN       128
#define NTILE    (K_CODES / BN)       // 32
#define NCHUNK   (NTILE * 4)          // 128 chunks of 64 dims
#define THREADS  256
#define MARGIN   6e-3f
#define CLB      8                    // flagged points per cleanup block
#define CLGRID   128                  // capacity 1024 points, 1 sweep/block

// mma smem layout (bytes)
#define SM_CSQ  0                      // 4096 f32 = 16 KB
#define SM_A    16384                  // 128 rows x 512 B (fp16) = 64 KB
#define SM_B    81920                  // 2 x 16 KB chunk buffers
#define SMEM_DYN 114688                // 112 KB -> 2 CTAs/SM

// cleanup smem (floats): sx[8][256], then 2 x sc[64][260]
#define CL_SC_OFF  (CLB * DIM)
#define CL_BUFF    (64 * 260)
#define CL_SMEM    ((CLB * DIM + 2 * CL_BUFF) * 4)   // 141312 B

typedef unsigned int uint32;

// ---------------------------------------------------------------------------
__device__ float  g_csq[K_CODES];
__device__ int    g_idx[N_POINTS];
__device__ double g_acc;
__device__ int    g_nflag;
__device__ int    g_flag[N_POINTS];
__device__ __align__(128) __half g_cbh[K_CODES * DIM];

// ---------------------------------------------------------------------------
__device__ __forceinline__ uint32 smem_u32(const void* p) {
    return (uint32)__cvta_generic_to_shared(p);
}
__device__ __forceinline__ void cp_async16(uint32 dst, const void* src) {
    asm volatile("cp.async.cg.shared.global [%0], [%1], 16;" :: "r"(dst), "l"(src));
}
#define CP_COMMIT()  asm volatile("cp.async.commit_group;" ::: "memory")
#define CP_WAIT(n)   asm volatile("cp.async.wait_group %0;" :: "n"(n) : "memory")
#define BAR_SYNC(id) asm volatile("bar.sync %0, 128;" :: "r"(id) : "memory")

__device__ __forceinline__ void ldsm4(uint32* r, uint32 addr) {
    asm volatile("ldmatrix.sync.aligned.m8n8.x4.shared.b16 {%0,%1,%2,%3}, [%4];"
                 : "=r"(r[0]), "=r"(r[1]), "=r"(r[2]), "=r"(r[3]) : "r"(addr));
}
__device__ __forceinline__ void mma16816(float* d, const uint32* a, const uint32* b) {
    asm volatile("mma.sync.aligned.m16n8k16.row.col.f32.f16.f16.f32 "
                 "{%0,%1,%2,%3}, {%4,%5,%6,%7}, {%8,%9}, {%0,%1,%2,%3};"
                 : "+f"(d[0]), "+f"(d[1]), "+f"(d[2]), "+f"(d[3])
                 : "r"(a[0]), "r"(a[1]), "r"(a[2]), "r"(a[3]), "r"(b[0]), "r"(b[1]));
}

// ---------------------------------------------------------------------------
__global__ void vq_reset_kernel() { g_acc = 0.0; g_nflag = 0; }

__global__ void vq_csq_kernel(const float* __restrict__ cb) {
    int row = blockIdx.x;
    float4 v = reinterpret_cast<const float4*>(cb + (size_t)row * DIM)[threadIdx.x];
    float s = v.x * v.x + v.y * v.y + v.z * v.z + v.w * v.w;
    #pragma unroll
    for (int o = 16; o > 0; o >>= 1) s += __shfl_xor_sync(0xffffffffu, s, o);
    __shared__ float ws[2];
    if ((threadIdx.x & 31) == 0) ws[threadIdx.x >> 5] = s;
    __syncthreads();
    if (threadIdx.x == 0) g_csq[row] = ws[0] + ws[1];
}

__global__ void vq_cbhalf_kernel(const float* __restrict__ cb) {
    for (int e = blockIdx.x * blockDim.x + threadIdx.x; e < K_CODES * DIM;
         e += gridDim.x * blockDim.x)
        g_cbh[e] = __float2half_rn(cb[e]);
}

// ---------------------------------------------------------------------------
// Half-CTA chunk load: each half (wn) loads only its own 8 KB (its 64 codes).
__device__ __forceinline__ void load_chunk_half(uint32 smB, int it, int wn, int hr) {
    const int tile = it >> 2, kc = it & 3;
    const uint32 dst = smB + (uint32)(it & 1) * 16384;
    const __half* src = g_cbh + (size_t)tile * BN * DIM + kc * 64;
    #pragma unroll
    for (int r = 0; r < 4; r++) {
        int s = hr + r * 128;                // 0..511 within half
        int cl = s >> 3, seg = s & 7;
        int code = wn * 64 + cl;
        uint32 off = code * 128 + ((seg * 16) ^ ((code & 7) << 4));
        cp_async16(dst + off, src + (size_t)code * DIM + seg * 8);
    }
}

// ---------------------------------------------------------------------------
// 1-pass fp16 tensor-core argmin, warp tile m32 x n64, 2 CTAs/SM.
// Round-7 2-stage pipeline + fast-path epilogue + split half-CTA barriers.
__global__ __launch_bounds__(THREADS, 2)
void vq_mma_kernel(const float* __restrict__ x) {
    extern __shared__ unsigned char smb[];
    const uint32 sbase = smem_u32(smb);
    float* sCsq = reinterpret_cast<float*>(smb + SM_CSQ);

    const int tid  = threadIdx.x;
    const int lane = tid & 31;
    const int warp = tid >> 5;
    const int wm   = warp >> 1;
    const int wn   = warp & 1;
    const int hr   = (warp >> 1) * 32 + lane;   // rank within half (0..127)
    const int barid = wn + 1;
    const int pbase = blockIdx.x * BM;

    load_chunk_half(sbase + SM_B, 0, wn, hr);
    CP_COMMIT();

    for (int i = tid; i < K_CODES; i += THREADS) sCsq[i] = g_csq[i];

    // A tile: 128 pts x 256 dims -> fp16, swizzled rows of 512 B
    {
        const float4* xg = reinterpret_cast<const float4*>(x + (size_t)pbase * DIM);
        #pragma unroll
        for (int i = 0; i < 16; i++) {
            int idx = tid + i * THREADS;
            int row = idx >> 5, seg = idx & 31;
            float4 v0 = xg[row * 64 + seg * 2];
            float4 v1 = xg[row * 64 + seg * 2 + 1];
            __half h[8];
            h[0] = __float2half_rn(v0.x); h[1] = __float2half_rn(v0.y);
            h[2] = __float2half_rn(v0.z); h[3] = __float2half_rn(v0.w);
            h[4] = __float2half_rn(v1.x); h[5] = __float2half_rn(v1.y);
            h[6] = __float2half_rn(v1.z); h[7] = __float2half_rn(v1.w);
            uint32 off = row * 512 + ((seg * 16) ^ ((row & 7) << 4));
            *reinterpret_cast<uint4*>(smb + SM_A + off) = *reinterpret_cast<uint4*>(h);
        }
    }

    const uint32 a_row  = wm * 32 + (lane & 7) + ((lane >> 3) & 1) * 8;
    const uint32 a_k16  = ((lane >> 4) & 1) * 16;
    const uint32 swz    = (lane & 7) << 4;
    const uint32 aBase0 = sbase + SM_A + a_row * 512;
    const uint32 aBase1 = aBase0 + 16 * 512;
    const uint32 b_cloc = ((lane >> 4) & 1) * 8 + (lane & 7);
    const uint32 b_k16  = ((lane >> 3) & 1) * 16;

    float dacc[2][8][4];
    #pragma unroll
    for (int mi = 0; mi < 2; mi++)
        #pragma unroll
        for (int nf = 0; nf < 8; nf++)
            #pragma unroll
            for (int q = 0; q < 4; q++) dacc[mi][nf][q] = 0.f;

    float best[4] = {FLT_MAX, FLT_MAX, FLT_MAX, FLT_MAX};
    float sec [4] = {FLT_MAX, FLT_MAX, FLT_MAX, FLT_MAX};
    int   bidx[4] = {0, 0, 0, 0};

    __syncthreads();       // A + csq visible to all

    for (int it = 0; it < NCHUNK; it++) {
        const int tile = it >> 2, kc = it & 3;

        BAR_SYNC(barid);   // own half's readers of buf[(it+1)&1] done
        if (it + 1 < NCHUNK) load_chunk_half(sbase + SM_B, it + 1, wn, hr);
        CP_COMMIT();
        CP_WAIT(1);        // own cp.asyncs for chunk `it` complete
        BAR_SYNC(barid);   // whole half has chunk `it` visible

        const uint32 bBase = sbase + SM_B + (uint32)(it & 1) * 16384;

        #pragma unroll
        for (int ks = 0; ks < 4; ks++) {
            uint32 a0[4], a1[4];
            uint32 aoff = ((uint32)(kc * 128 + ks * 32) + a_k16) ^ swz;
            ldsm4(a0, aBase0 + aoff);
            ldsm4(a1, aBase1 + aoff);
            uint32 boff = ((uint32)(ks * 32) + b_k16) ^ swz;
            #pragma unroll
            for (int np = 0; np < 4; np++) {
                uint32 bh[4];
                ldsm4(bh, bBase + (uint32)(wn * 64 + np * 16 + b_cloc) * 128 + boff);
                mma16816(dacc[0][2 * np],     a0, bh);
                mma16816(dacc[1][2 * np],     a1, bh);
                mma16816(dacc[0][2 * np + 1], a0, bh + 2);
                mma16816(dacc[1][2 * np + 1], a1, bh + 2);
            }
        }

        if (kc == 3) {
            const int cb0 = tile * BN + wn * 64 + (lane & 3) * 2;
            float cs0v[8], cs1v[8];
            #pragma unroll
            for (int nf = 0; nf < 8; nf++) {
                float2 c2 = *reinterpret_cast<const float2*>(&sCsq[cb0 + nf * 8]);
                cs0v[nf] = c2.x; cs1v[nf] = c2.y;
            }
            #pragma unroll
            for (int mi = 0; mi < 2; mi++)
                #pragma unroll
                for (int q = 0; q < 2; q++) {
                    const int k = mi * 2 + q;
                    float s[16];
                    float tmin = FLT_MAX;
                    #pragma unroll
                    for (int nf = 0; nf < 8; nf++) {
                        float s0 = fmaf(-2.f, dacc[mi][nf][2 * q],     cs0v[nf]);
                        float s1 = fmaf(-2.f, dacc[mi][nf][2 * q + 1], cs1v[nf]);
                        s[2 * nf] = s0; s[2 * nf + 1] = s1;
                        tmin = fminf(tmin, fminf(s0, s1));
                        dacc[mi][nf][2 * q] = 0.f; dacc[mi][nf][2 * q + 1] = 0.f;
                    }
                    if (tmin <= sec[k]) {
                        #pragma unroll
                        for (int e = 0; e < 16; e++) {   // ascending ci
                            float sv = s[e];
                            int   ci = cb0 + (e >> 1) * 8 + (e & 1);
                            if (sv < best[k]) { sec[k] = best[k]; best[k] = sv; bidx[k] = ci; }
                            else if (sv < sec[k]) sec[k] = sv;
                        }
                    }
                }
        }
    }

    float mb[4], ms[4];
    int   mi_[4];
    #pragma unroll
    for (int k = 0; k < 4; k++) {
        float b = best[k], s = sec[k];
        int   i = bidx[k];
        #pragma unroll
        for (int off = 1; off <= 2; off <<= 1) {
            float ob = __shfl_xor_sync(0xffffffffu, b, off);
            float os = __shfl_xor_sync(0xffffffffu, s, off);
            int   oi = __shfl_xor_sync(0xffffffffu, i, off);
            if (ob < b)      { s = fminf(b, os); b = ob; i = oi; }
            else if (b < ob) { s = fminf(s, ob); }
            else             { s = b; i = min(i, oi); }
        }
        mb[k] = b; ms[k] = s; mi_[k] = i;
    }

    float* mB = reinterpret_cast<float*>(smb + SM_B);
    float* mS = mB + 256;
    int*   mI = reinterpret_cast<int*>(mS + 256);
    __syncthreads();
    if ((lane & 3) == 0) {
        #pragma unroll
        for (int k = 0; k < 4; k++) {
            int row = wm * 32 + (k >> 1) * 16 + (lane >> 2) + (k & 1) * 8;
            int s2  = wn * 128 + row;
            mB[s2] = mb[k]; mS[s2] = ms[k]; mI[s2] = mi_[k];
        }
    }
    __syncthreads();
    if (tid < BM) {
        float b0 = mB[tid], s0 = mS[tid], b1 = mB[128 + tid], s1 = mS[128 + tid];
        int   i0 = mI[tid], i1 = mI[128 + tid];
        float b, s; int i;
        if (b0 < b1)      { b = b0; i = i0; s = fminf(s0, b1); }
        else if (b1 < b0) { b = b1; i = i1; s = fminf(s1, b0); }
        else              { b = b0; i = min(i0, i1); s = b0; }
        const int pg = pbase + tid;
        if (s - b <= MARGIN) {
            int pos = atomicAdd(&g_nflag, 1);
            g_flag[pos] = pg;
        } else {
            g_idx[pg] = i;
        }
    }
}

// ---------------------------------------------------------------------------
// Exact fp32 resolution for flagged points. 8 points/block, 64-code tiles,
// cp.async double-buffered so tile loads overlap compute. Per-code summation
// order is the frozen sequential x.x,y,z,w chain (load-bearing, see round 8).
__global__ __launch_bounds__(256, 1)
void vq_cleanup_kernel(const float* __restrict__ x, const float* __restrict__ cb) {
    extern __shared__ float clsm[];
    float* sx = clsm;                          // [CLB][DIM]
    const uint32 scb = smem_u32(clsm + CL_SC_OFF);
    const int tid  = threadIdx.x;
    const int lane = tid & 31;
    const int w    = tid >> 5;
    const int nf   = g_nflag;

    for (int g = blockIdx.x * CLB; g < nf; g += gridDim.x * CLB) {
        const int npts = min(CLB, nf - g);
        __syncthreads();                       // protect sx/buffers across groups
        for (int i = tid; i < npts * D4; i += 256) {
            int pt = i >> 6, c4 = i & 63;
            int p = g_flag[g + pt];
            *reinterpret_cast<float4*>(&sx[pt * DIM + c4 * 4]) =
                reinterpret_cast<const float4*>(x)[(size_t)p * D4 + c4];
        }

        // Prologue: tile 0 -> buf 0
        #pragma unroll
        for (int r = 0; r < 16; r++) {
            int i = tid + r * 256;             // 0..4095 16B-segments
            int cr = i >> 6, seg = i & 63;
            cp_async16(scb + cr * 1040 + seg * 16,
                       cb + (size_t)cr * DIM + seg * 4);
        }
        CP_COMMIT();

        float best = FLT_MAX;
        int   bi   = 0x7fffffff;

        for (int t = 0; t < K_CODES / 64; t++) {
            __syncthreads();                   // readers of buf[(t+1)&1] done
            if (t + 1 < K_CODES / 64) {
                const uint32 dstb = scb + (uint32)((t + 1) & 1) * (CL_BUFF * 4);
                const float* srcb = cb + (size_t)(t + 1) * 64 * DIM;
                #pragma unroll
                for (int r = 0; r < 16; r++) {
                    int i = tid + r * 256;
                    int cr = i >> 6, seg = i & 63;
                    cp_async16(dstb + cr * 1040 + seg * 16,
                               srcb + (size_t)cr * DIM + seg * 4);
                }
            }
            CP_COMMIT();
            CP_WAIT(1);                        // tile t resident
            __syncthreads();

            if (w < npts) {
                const float* sc = clsm + CL_SC_OFF + (t & 1) * CL_BUFF;
                const float* xr = &sx[w * DIM];
                const float* cA = &sc[lane * 260];
                const float* cB = &sc[(lane + 32) * 260];
                float dA = 0.f, dB = 0.f;
                #pragma unroll 16
                for (int k = 0; k < D4; k++) {
                    float4 xv = *reinterpret_cast<const float4*>(&xr[k * 4]);
                    float4 av = *reinterpret_cast<const float4*>(&cA[k * 4]);
                    float4 bv = *reinterpret_cast<const float4*>(&cB[k * 4]);
                    dA = fmaf(xv.x, av.x, dA); dA = fmaf(xv.y, av.y, dA);
                    dA = fmaf(xv.z, av.z, dA); dA = fmaf(xv.w, av.w, dA);
                    dB = fmaf(xv.x, bv.x, dB); dB = fmaf(xv.y, bv.y, dB);
                    dB = fmaf(xv.z, bv.z, dB); dB = fmaf(xv.w, bv.w, dB);
                }
                const int ciA = t * 64 + lane;
                const int ciB = ciA + 32;
                float sA = fmaf(-2.f, dA, __ldg(&g_csq[ciA]));
                float sB = fmaf(-2.f, dB, __ldg(&g_csq[ciB]));
                if (sA < best) { best = sA; bi = ciA; }   // A first: ascending ci
                if (sB < best) { best = sB; bi = ciB; }
            }
        }

        #pragma unroll
        for (int off = 16; off > 0; off >>= 1) {
            float ob = __shfl_xor_sync(0xffffffffu, best, off);
            int   oi = __shfl_xor_sync(0xffffffffu, bi, off);
            if (ob < best || (ob == best && oi < bi)) { best = ob; bi = oi; }
        }
        if (lane == 0 && w < npts) g_idx[g_flag[g + w]] = bi;
    }
}

// ---------------------------------------------------------------------------
__global__ void vq_gather_kernel(const float* __restrict__ x,
                                 const float* __restrict__ cb,
                                 float* __restrict__ out) {
    const int total4 = N_POINTS * D4;
    float part = 0.f;
    for (int i4 = blockIdx.x * blockDim.x + threadIdx.x; i4 < total4;
         i4 += gridDim.x * blockDim.x) {
        int p  = i4 >> 6;
        int c4 = i4 & 63;
        int ci = g_idx[p];
        float4 xv = reinterpret_cast<const float4*>(x)[i4];
        float4 qv = reinterpret_cast<const float4*>(cb)[(size_t)ci * D4 + c4];
        float4 d, o;
        d.x = qv.x - xv.x; d.y = qv.y - xv.y; d.z = qv.z - xv.z; d.w = qv.w - xv.w;
        o.x = xv.x + d.x;  o.y = xv.y + d.y;  o.z = xv.z + d.z;  o.w = xv.w + d.w;
        reinterpret_cast<float4*>(out)[i4] = o;
        part += d.x * d.x + d.y * d.y + d.z * d.z + d.w * d.w;
    }
    #pragma unroll
    for (int o = 16; o > 0; o >>= 1) part += __shfl_xor_sync(0xffffffffu, part, o);
    __shared__ float ws[8];
    if ((threadIdx.x & 31) == 0) ws[threadIdx.x >> 5] = part;
    __syncthreads();
    if (threadIdx.x == 0) {
        float bs = 0.f;
        for (int w = 0; w < (int)(blockDim.x >> 5); w++) bs += ws[w];
        atomicAdd(&g_acc, (double)bs);
    }
}

// ---------------------------------------------------------------------------
__global__ void vq_finalize_kernel(float* __restrict__ out) {
    out[(size_t)N_POINTS * DIM] = (float)(1.25 * g_acc / (double)(N_POINTS * DIM));
}

// ---------------------------------------------------------------------------
extern "C" void kernel_launch(void* const* d_in, const int* in_sizes, int n_in,
                              void* d_out, int out_size) {
    const float* x  = (const float*)d_in[0];
    const float* cb = (const float*)d_in[1];
    float* out = (float*)d_out;
    (void)in_sizes; (void)n_in; (void)out_size;

    cudaFuncSetAttribute(vq_mma_kernel, cudaFuncAttributeMaxDynamicSharedMemorySize,
                         SMEM_DYN);
    cudaFuncSetAttribute(vq_cleanup_kernel, cudaFuncAttributeMaxDynamicSharedMemorySize,
                         CL_SMEM);

    vq_reset_kernel<<<1, 1>>>();
    vq_csq_kernel<<<K_CODES, 64>>>(cb);
    vq_cbhalf_kernel<<<1024, 256>>>(cb);
    vq_mma_kernel<<<N_POINTS / BM, THREADS, SMEM_DYN>>>(x);
    vq_cleanup_kernel<<<CLGRID, 256, CL_SMEM>>>(x, cb);
    vq_gather_kernel<<<4096, 256>>>(x, cb, out);
    vq_finalize_kernel<<<1, 1>>>(out);
}

// round 11
// speedup vs baseline: 5.9670x; 1.2605x over previous
#include <cuda_runtime.h>
#include <cuda_fp16.h>
#include <cfloat>
#include <cstdint>

#define N_POINTS 32768
#define DIM      256
#define D4       (DIM / 4)
#define K_CODES  4096
#define BM       128
#define BN       128
#define NTILE    (K_CODES / BN)       // 32
#define NCHUNK   (NTILE * 4)          // 128 chunks of 64 dims
#define THREADS  256
#define MARGIN   6e-3f
#define CLB      8                    // flagged points per cleanup group
#define KSPLIT   4                    // codebook chunks per group (1024 codes)
#define CLTC     32                   // codes per cleanup smem tile
#define CLGRID   512

// mma smem layout (bytes)
#define SM_CSQ  0                      // 4096 f32 = 16 KB
#define SM_A    16384                  // 128 rows x 512 B (fp16) = 64 KB
#define SM_B    81920                  // 2 x 16 KB chunk buffers
#define SMEM_DYN 114688                // 112 KB -> 2 CTAs/SM

// cleanup smem (floats): sx[8][260], 2 x sc[32][260]
#define CL_SX_F   (CLB * 260)          // 2080
#define CL_BUF_F  (CLTC * 260)         // 8320
#define CL_SMEM   ((CL_SX_F + 2 * CL_BUF_F) * 4)   // 74880 B -> 2 CTAs/SM

typedef unsigned int uint32;
typedef unsigned long long ull;

// ---------------------------------------------------------------------------
__device__ float  g_csq[K_CODES];
__device__ int    g_idx[N_POINTS];
__device__ double g_acc;
__device__ int    g_nflag;
__device__ int    g_flag[N_POINTS];
__device__ ull    g_pack[N_POINTS];
__device__ __align__(128) __half g_cbh[K_CODES * DIM];

// ---------------------------------------------------------------------------
__device__ __forceinline__ uint32 smem_u32(const void* p) {
    return (uint32)__cvta_generic_to_shared(p);
}
__device__ __forceinline__ void cp_async16(uint32 dst, const void* src) {
    asm volatile("cp.async.cg.shared.global [%0], [%1], 16;" :: "r"(dst), "l"(src));
}
#define CP_COMMIT()  asm volatile("cp.async.commit_group;" ::: "memory")
#define CP_WAIT(n)   asm volatile("cp.async.wait_group %0;" :: "n"(n) : "memory")
#define BAR_SYNC(id) asm volatile("bar.sync %0, 128;" :: "r"(id) : "memory")

__device__ __forceinline__ void ldsm4(uint32* r, uint32 addr) {
    asm volatile("ldmatrix.sync.aligned.m8n8.x4.shared.b16 {%0,%1,%2,%3}, [%4];"
                 : "=r"(r[0]), "=r"(r[1]), "=r"(r[2]), "=r"(r[3]) : "r"(addr));
}
__device__ __forceinline__ void mma16816(float* d, const uint32* a, const uint32* b) {
    asm volatile("mma.sync.aligned.m16n8k16.row.col.f32.f16.f16.f32 "
                 "{%0,%1,%2,%3}, {%4,%5,%6,%7}, {%8,%9}, {%0,%1,%2,%3};"
                 : "+f"(d[0]), "+f"(d[1]), "+f"(d[2]), "+f"(d[3])
                 : "r"(a[0]), "r"(a[1]), "r"(a[2]), "r"(a[3]), "r"(b[0]), "r"(b[1]));
}
// Monotonic float->uint map; key = (ordered(score) << 32) | idx.
// min(key) == lexicographic (score, idx) min == first-occurrence argmin.
__device__ __forceinline__ ull score_key(float s, int idx) {
    uint32 u = __float_as_uint(s);
    u = (u & 0x80000000u) ? ~u : (u | 0x80000000u);
    return ((ull)u << 32) | (uint32)idx;
}

// ---------------------------------------------------------------------------
__global__ void vq_reset_kernel() { g_acc = 0.0; g_nflag = 0; }

__global__ void vq_csq_kernel(const float* __restrict__ cb) {
    int row = blockIdx.x;
    float4 v = reinterpret_cast<const float4*>(cb + (size_t)row * DIM)[threadIdx.x];
    float s = v.x * v.x + v.y * v.y + v.z * v.z + v.w * v.w;
    #pragma unroll
    for (int o = 16; o > 0; o >>= 1) s += __shfl_xor_sync(0xffffffffu, s, o);
    __shared__ float ws[2];
    if ((threadIdx.x & 31) == 0) ws[threadIdx.x >> 5] = s;
    __syncthreads();
    if (threadIdx.x == 0) g_csq[row] = ws[0] + ws[1];
}

__global__ void vq_cbhalf_kernel(const float* __restrict__ cb) {
    for (int e = blockIdx.x * blockDim.x + threadIdx.x; e < K_CODES * DIM;
         e += gridDim.x * blockDim.x)
        g_cbh[e] = __float2half_rn(cb[e]);
}

// ---------------------------------------------------------------------------
__device__ __forceinline__ void load_chunk_half(uint32 smB, int it, int wn, int hr) {
    const int tile = it >> 2, kc = it & 3;
    const uint32 dst = smB + (uint32)(it & 1) * 16384;
    const __half* src = g_cbh + (size_t)tile * BN * DIM + kc * 64;
    #pragma unroll
    for (int r = 0; r < 4; r++) {
        int s = hr + r * 128;
        int cl = s >> 3, seg = s & 7;
        int code = wn * 64 + cl;
        uint32 off = code * 128 + ((seg * 16) ^ ((code & 7) << 4));
        cp_async16(dst + off, src + (size_t)code * DIM + seg * 8);
    }
}

// ---------------------------------------------------------------------------
// 1-pass fp16 tensor-core argmin (unchanged from round 10 except g_pack init).
__global__ __launch_bounds__(THREADS, 2)
void vq_mma_kernel(const float* __restrict__ x) {
    extern __shared__ unsigned char smb[];
    const uint32 sbase = smem_u32(smb);
    float* sCsq = reinterpret_cast<float*>(smb + SM_CSQ);

    const int tid  = threadIdx.x;
    const int lane = tid & 31;
    const int warp = tid >> 5;
    const int wm   = warp >> 1;
    const int wn   = warp & 1;
    const int hr   = (warp >> 1) * 32 + lane;
    const int barid = wn + 1;
    const int pbase = blockIdx.x * BM;

    load_chunk_half(sbase + SM_B, 0, wn, hr);
    CP_COMMIT();

    for (int i = tid; i < K_CODES; i += THREADS) sCsq[i] = g_csq[i];

    {
        const float4* xg = reinterpret_cast<const float4*>(x + (size_t)pbase * DIM);
        #pragma unroll
        for (int i = 0; i < 16; i++) {
            int idx = tid + i * THREADS;
            int row = idx >> 5, seg = idx & 31;
            float4 v0 = xg[row * 64 + seg * 2];
            float4 v1 = xg[row * 64 + seg * 2 + 1];
            __half h[8];
            h[0] = __float2half_rn(v0.x); h[1] = __float2half_rn(v0.y);
            h[2] = __float2half_rn(v0.z); h[3] = __float2half_rn(v0.w);
            h[4] = __float2half_rn(v1.x); h[5] = __float2half_rn(v1.y);
            h[6] = __float2half_rn(v1.z); h[7] = __float2half_rn(v1.w);
            uint32 off = row * 512 + ((seg * 16) ^ ((row & 7) << 4));
            *reinterpret_cast<uint4*>(smb + SM_A + off) = *reinterpret_cast<uint4*>(h);
        }
    }

    const uint32 a_row  = wm * 32 + (lane & 7) + ((lane >> 3) & 1) * 8;
    const uint32 a_k16  = ((lane >> 4) & 1) * 16;
    const uint32 swz    = (lane & 7) << 4;
    const uint32 aBase0 = sbase + SM_A + a_row * 512;
    const uint32 aBase1 = aBase0 + 16 * 512;
    const uint32 b_cloc = ((lane >> 4) & 1) * 8 + (lane & 7);
    const uint32 b_k16  = ((lane >> 3) & 1) * 16;

    float dacc[2][8][4];
    #pragma unroll
    for (int mi = 0; mi < 2; mi++)
        #pragma unroll
        for (int nf = 0; nf < 8; nf++)
            #pragma unroll
            for (int q = 0; q < 4; q++) dacc[mi][nf][q] = 0.f;

    float best[4] = {FLT_MAX, FLT_MAX, FLT_MAX, FLT_MAX};
    float sec [4] = {FLT_MAX, FLT_MAX, FLT_MAX, FLT_MAX};
    int   bidx[4] = {0, 0, 0, 0};

    __syncthreads();

    for (int it = 0; it < NCHUNK; it++) {
        const int tile = it >> 2, kc = it & 3;

        BAR_SYNC(barid);
        if (it + 1 < NCHUNK) load_chunk_half(sbase + SM_B, it + 1, wn, hr);
        CP_COMMIT();
        CP_WAIT(1);
        BAR_SYNC(barid);

        const uint32 bBase = sbase + SM_B + (uint32)(it & 1) * 16384;

        #pragma unroll
        for (int ks = 0; ks < 4; ks++) {
            uint32 a0[4], a1[4];
            uint32 aoff = ((uint32)(kc * 128 + ks * 32) + a_k16) ^ swz;
            ldsm4(a0, aBase0 + aoff);
            ldsm4(a1, aBase1 + aoff);
            uint32 boff = ((uint32)(ks * 32) + b_k16) ^ swz;
            #pragma unroll
            for (int np = 0; np < 4; np++) {
                uint32 bh[4];
                ldsm4(bh, bBase + (uint32)(wn * 64 + np * 16 + b_cloc) * 128 + boff);
                mma16816(dacc[0][2 * np],     a0, bh);
                mma16816(dacc[1][2 * np],     a1, bh);
                mma16816(dacc[0][2 * np + 1], a0, bh + 2);
                mma16816(dacc[1][2 * np + 1], a1, bh + 2);
            }
        }

        if (kc == 3) {
            const int cb0 = tile * BN + wn * 64 + (lane & 3) * 2;
            float cs0v[8], cs1v[8];
            #pragma unroll
            for (int nf = 0; nf < 8; nf++) {
                float2 c2 = *reinterpret_cast<const float2*>(&sCsq[cb0 + nf * 8]);
                cs0v[nf] = c2.x; cs1v[nf] = c2.y;
            }
            #pragma unroll
            for (int mi = 0; mi < 2; mi++)
                #pragma unroll
                for (int q = 0; q < 2; q++) {
                    const int k = mi * 2 + q;
                    float s[16];
                    float tmin = FLT_MAX;
                    #pragma unroll
                    for (int nf = 0; nf < 8; nf++) {
                        float s0 = fmaf(-2.f, dacc[mi][nf][2 * q],     cs0v[nf]);
                        float s1 = fmaf(-2.f, dacc[mi][nf][2 * q + 1], cs1v[nf]);
                        s[2 * nf] = s0; s[2 * nf + 1] = s1;
                        tmin = fminf(tmin, fminf(s0, s1));
                        dacc[mi][nf][2 * q] = 0.f; dacc[mi][nf][2 * q + 1] = 0.f;
                    }
                    if (tmin <= sec[k]) {
                        #pragma unroll
                        for (int e = 0; e < 16; e++) {
                            float sv = s[e];
                            int   ci = cb0 + (e >> 1) * 8 + (e & 1);
                            if (sv < best[k]) { sec[k] = best[k]; best[k] = sv; bidx[k] = ci; }
                            else if (sv < sec[k]) sec[k] = sv;
                        }
                    }
                }
        }
    }

    float mb[4], ms[4];
    int   mi_[4];
    #pragma unroll
    for (int k = 0; k < 4; k++) {
        float b = best[k], s = sec[k];
        int   i = bidx[k];
        #pragma unroll
        for (int off = 1; off <= 2; off <<= 1) {
            float ob = __shfl_xor_sync(0xffffffffu, b, off);
            float os = __shfl_xor_sync(0xffffffffu, s, off);
            int   oi = __shfl_xor_sync(0xffffffffu, i, off);
            if (ob < b)      { s = fminf(b, os); b = ob; i = oi; }
            else if (b < ob) { s = fminf(s, ob); }
            else             { s = b; i = min(i, oi); }
        }
        mb[k] = b; ms[k] = s; mi_[k] = i;
    }

    float* mB = reinterpret_cast<float*>(smb + SM_B);
    float* mS = mB + 256;
    int*   mI = reinterpret_cast<int*>(mS + 256);
    __syncthreads();
    if ((lane & 3) == 0) {
        #pragma unroll
        for (int k = 0; k < 4; k++) {
            int row = wm * 32 + (k >> 1) * 16 + (lane >> 2) + (k & 1) * 8;
            int s2  = wn * 128 + row;
            mB[s2] = mb[k]; mS[s2] = ms[k]; mI[s2] = mi_[k];
        }
    }
    __syncthreads();
    if (tid < BM) {
        float b0 = mB[tid], s0 = mS[tid], b1 = mB[128 + tid], s1 = mS[128 + tid];
        int   i0 = mI[tid], i1 = mI[128 + tid];
        float b, s; int i;
        if (b0 < b1)      { b = b0; i = i0; s = fminf(s0, b1); }
        else if (b1 < b0) { b = b1; i = i1; s = fminf(s1, b0); }
        else              { b = b0; i = min(i0, i1); s = b0; }
        const int pg = pbase + tid;
        if (s - b <= MARGIN) {
            int pos = atomicAdd(&g_nflag, 1);
            g_flag[pos] = pg;
            g_pack[pos] = 0xFFFFFFFFFFFFFFFFull;   // init merge target
        } else {
            g_idx[pg] = i;
        }
    }
}

// ---------------------------------------------------------------------------
// Exact fp32 resolution, v3: work item = (8-point group) x (1024-code chunk).
// Lane l of warp w: point l>>2, code w*4 + (l&3) within each 32-code tile —
// one code-row load serves 8 points (8x less crossbar traffic than v2).
// Per-(pt,code) dot keeps the frozen sequential x.x,y,z,w dim chain.
// Cross-block merge via atomicMin on packed (orderedScore, idx) keys.
__global__ __launch_bounds__(256, 2)
void vq_cleanup_kernel(const float* __restrict__ x, const float* __restrict__ cb) {
    extern __shared__ float clsm[];
    float* sx = clsm;                          // [CLB][260]
    float* sc0 = clsm + CL_SX_F;               // [2][CLTC][260]
    const uint32 scb = smem_u32(sc0);
    const int tid  = threadIdx.x;
    const int lane = tid & 31;
    const int w    = tid >> 5;
    const int pt   = lane >> 2;                // 0..7
    const int cit  = w * 4 + (lane & 3);       // 0..31 code within tile
    const int nf   = g_nflag;
    const int ngroups = (nf + CLB - 1) / CLB;
    const int nwork = ngroups * KSPLIT;

    for (int work = blockIdx.x; work < nwork; work += gridDim.x) {
        const int g     = (work / KSPLIT) * CLB;
        const int cbase = (work % KSPLIT) * (K_CODES / KSPLIT);
        const int npts  = min(CLB, nf - g);
        __syncthreads();                       // protect sx/buffers across works
        for (int i = tid; i < npts * D4; i += 256) {
            int p2 = i >> 6, c4 = i & 63;
            int p = g_flag[g + p2];
            *reinterpret_cast<float4*>(&sx[p2 * 260 + c4 * 4]) =
                reinterpret_cast<const float4*>(x)[(size_t)p * D4 + c4];
        }

        // Prologue: tile 0 -> buf 0 (32 rows x 64 segs = 2048 / 256 thr = 8 ea)
        #pragma unroll
        for (int r = 0; r < 8; r++) {
            int i = tid + r * 256;
            int cr = i >> 6, seg = i & 63;
            cp_async16(scb + cr * 1040 + seg * 16,
                       cb + (size_t)(cbase + cr) * DIM + seg * 4);
        }
        CP_COMMIT();

        float best = FLT_MAX;
        int   bi   = 0x7fffffff;
        const int ntiles = (K_CODES / KSPLIT) / CLTC;   // 32

        for (int t = 0; t < ntiles; t++) {
            __syncthreads();                   // readers of buf[(t+1)&1] done
            if (t + 1 < ntiles) {
                const uint32 dstb = scb + (uint32)((t + 1) & 1) * (CL_BUF_F * 4);
                const float* srcb = cb + (size_t)(cbase + (t + 1) * CLTC) * DIM;
                #pragma unroll
                for (int r = 0; r < 8; r++) {
                    int i = tid + r * 256;
                    int cr = i >> 6, seg = i & 63;
                    cp_async16(dstb + cr * 1040 + seg * 16,
                               srcb + (size_t)cr * DIM + seg * 4);
                }
            }
            CP_COMMIT();
            CP_WAIT(1);                        // tile t resident
            __syncthreads();

            if (pt < npts) {
                const float* xr = &sx[pt * 260];
                const float* cr = &sc0[(t & 1) * CL_BUF_F + cit * 260];
                float d = 0.f;
                #pragma unroll 16
                for (int k = 0; k < D4; k++) {
                    float4 xv = *reinterpret_cast<const float4*>(&xr[k * 4]);
                    float4 cv = *reinterpret_cast<const float4*>(&cr[k * 4]);
                    d = fmaf(xv.x, cv.x, d); d = fmaf(xv.y, cv.y, d);
                    d = fmaf(xv.z, cv.z, d); d = fmaf(xv.w, cv.w, d);
                }
                const int ci = cbase + t * CLTC + cit;
                float s = fmaf(-2.f, d, __ldg(&g_csq[ci]));
                if (s < best) { best = s; bi = ci; }   // t ascending => ci ascending
            }
        }

        // Merge the 4 lanes of each quad (same pt, different codes), lexicographic
        #pragma unroll
        for (int off = 1; off <= 2; off <<= 1) {
            float ob = __shfl_xor_sync(0xffffffffu, best, off);
            int   oi = __shfl_xor_sync(0xffffffffu, bi, off);
            if (ob < best || (ob == best && oi < bi)) { best = ob; bi = oi; }
        }
        if ((lane & 3) == 0 && pt < npts)
            atomicMin(&g_pack[g + pt], score_key(best, bi));
    }
}

// ---------------------------------------------------------------------------
__global__ void vq_writeback_kernel() {
    int i = blockIdx.x * blockDim.x + threadIdx.x;
    if (i < g_nflag)
        g_idx[g_flag[i]] = (int)(g_pack[i] & 0xFFFFFFFFull);
}

// ---------------------------------------------------------------------------
__global__ void vq_gather_kernel(const float* __restrict__ x,
                                 const float* __restrict__ cb,
                                 float* __restrict__ out) {
    const int total4 = N_POINTS * D4;
    float part = 0.f;
    for (int i4 = blockIdx.x * blockDim.x + threadIdx.x; i4 < total4;
         i4 += gridDim.x * blockDim.x) {
        int p  = i4 >> 6;
        int c4 = i4 & 63;
        int ci = g_idx[p];
        float4 xv = reinterpret_cast<const float4*>(x)[i4];
        float4 qv = reinterpret_cast<const float4*>(cb)[(size_t)ci * D4 + c4];
        float4 d, o;
        d.x = qv.x - xv.x; d.y = qv.y - xv.y; d.z = qv.z - xv.z; d.w = qv.w - xv.w;
        o.x = xv.x + d.x;  o.y = xv.y + d.y;  o.z = xv.z + d.z;  o.w = xv.w + d.w;
        reinterpret_cast<float4*>(out)[i4] = o;
        part += d.x * d.x + d.y * d.y + d.z * d.z + d.w * d.w;
    }
    #pragma unroll
    for (int o = 16; o > 0; o >>= 1) part += __shfl_xor_sync(0xffffffffu, part, o);
    __shared__ float ws[8];
    if ((threadIdx.x & 31) == 0) ws[threadIdx.x >> 5] = part;
    __syncthreads();
    if (threadIdx.x == 0) {
        float bs = 0.f;
        for (int w = 0; w < (int)(blockDim.x >> 5); w++) bs += ws[w];
        atomicAdd(&g_acc, (double)bs);
    }
}

// ---------------------------------------------------------------------------
__global__ void vq_finalize_kernel(float* __restrict__ out) {
    out[(size_t)N_POINTS * DIM] = (float)(1.25 * g_acc / (double)(N_POINTS * DIM));
}

// ---------------------------------------------------------------------------
extern "C" void kernel_launch(void* const* d_in, const int* in_sizes, int n_in,
                              void* d_out, int out_size) {
    const float* x  = (const float*)d_in[0];
    const float* cb = (const float*)d_in[1];
    float* out = (float*)d_out;
    (void)in_sizes; (void)n_in; (void)out_size;

    cudaFuncSetAttribute(vq_mma_kernel, cudaFuncAttributeMaxDynamicSharedMemorySize,
                         SMEM_DYN);
    cudaFuncSetAttribute(vq_cleanup_kernel, cudaFuncAttributeMaxDynamicSharedMemorySize,
                         CL_SMEM);

    vq_reset_kernel<<<1, 1>>>();
    vq_csq_kernel<<<K_CODES, 64>>>(cb);
    vq_cbhalf_kernel<<<1024, 256>>>(cb);
    vq_mma_kernel<<<N_POINTS / BM, THREADS, SMEM_DYN>>>(x);
    vq_cleanup_kernel<<<CLGRID, 256, CL_SMEM>>>(x, cb);
    vq_writeback_kernel<<<128, 256>>>();
    vq_gather_kernel<<<4096, 256>>>(x, cb, out);
    vq_finalize_kernel<<<1, 1>>>(out);
}